// round 2
// baseline (speedup 1.0000x reference)
#include <cuda_runtime.h>
#include <math.h>

#define Bb 64
#define Nn 1024
#define Dd 512
#define TOT (Bb*Nn*Dd)
#define NUMIT 4
#define EPSc 1e-8f

// Scratch (device globals — no runtime allocation allowed)
__device__ float g_z[TOT];                 // ADMM dual z (B,N,D)
__device__ float g_c[TOT];                 // combined c = log_s - z/rho_next
__device__ float g_m[NUMIT][Bb*Dd];        // log_mu stage used by row-kernel k
__device__ float g_e[NUMIT][Bb*Nn];        // log_eta stage used by col-kernel k

__device__ __forceinline__ float warpMax(float v){
#pragma unroll
    for (int o = 16; o > 0; o >>= 1) v = fmaxf(v, __shfl_xor_sync(0xffffffffu, v, o));
    return v;
}
__device__ __forceinline__ float warpSum(float v){
#pragma unroll
    for (int o = 16; o > 0; o >>= 1) v += __shfl_xor_sync(0xffffffffu, v, o);
    return v;
}

// ---------------------------------------------------------------------------
// Precompute the full log_mu / log_eta trajectories (dual marginals separable:
// the (B,N,D)-shaped parts of z1/z2 cancel inside their logsumexps).
// ---------------------------------------------------------------------------
__global__ void __launch_bounds__(512) precomp_kernel(
    const float* __restrict__ p0, const float* __restrict__ q0,
    const float* __restrict__ a2, const float* __restrict__ a3,
    const float* __restrict__ rho)
{
    __shared__ float red[32];
    int b = blockIdx.x, tid = threadIdx.x;
    int wid = tid >> 5, lane = tid & 31;

    // ---- mu chain: D=512, one element per thread ----
    float lp = logf(p0[b*Dd + tid]);
    float m = lp, A = 0.f;
    g_m[0][b*Dd + tid] = lp;
    for (int kk = 0; kk < NUMIT-1; kk++){
        float r = rho[kk], a = a2[kk];
        float g = (r*m + a*lp - A) / (r + a);
        float v = warpMax(g);
        if (lane == 0) red[wid] = v;
        __syncthreads();
        if (wid == 0){ float u = (lane < 16) ? red[lane] : -3.4e38f; u = warpMax(u); if (lane==0) red[16]=u; }
        __syncthreads();
        float mx = red[16];
        __syncthreads();
        float s = warpSum(expf(g - mx));
        if (lane == 0) red[wid] = s;
        __syncthreads();
        if (wid == 0){ float u = (lane < 16) ? red[lane] : 0.f; u = warpSum(u); if (lane==0) red[16]=u; }
        __syncthreads();
        float L = mx + logf(red[16]);
        __syncthreads();
        m = g - L;
        A += r * expf(m);
        g_m[kk+1][b*Dd + tid] = m;
    }

    // ---- eta chain: N=1024, two elements per thread ----
    float lq0 = logf(q0[b*Nn + tid] + EPSc);
    float lq1 = logf(q0[b*Nn + tid + 512] + EPSc);
    float e0 = lq0, e1 = lq1, C0 = 0.f, C1 = 0.f;
    g_e[0][b*Nn + tid]       = e0;
    g_e[0][b*Nn + tid + 512] = e1;
    for (int kk = 0; kk < NUMIT-1; kk++){
        float r = rho[kk], a = a3[kk];
        float h0 = (r*e0 + a*lq0 - C0) / (r + a);
        float h1 = (r*e1 + a*lq1 - C1) / (r + a);
        float v = warpMax(fmaxf(h0, h1));
        if (lane == 0) red[wid] = v;
        __syncthreads();
        if (wid == 0){ float u = (lane < 16) ? red[lane] : -3.4e38f; u = warpMax(u); if (lane==0) red[16]=u; }
        __syncthreads();
        float mx = red[16];
        __syncthreads();
        float s = warpSum(expf(h0 - mx) + expf(h1 - mx));
        if (lane == 0) red[wid] = s;
        __syncthreads();
        if (wid == 0){ float u = (lane < 16) ? red[lane] : 0.f; u = warpSum(u); if (lane==0) red[16]=u; }
        __syncthreads();
        float L = mx + logf(red[16]);
        __syncthreads();
        e0 = h0 - L; e1 = h1 - L;
        C0 += r * expf(e0); C1 += r * expf(e1);
        g_e[kk+1][b*Nn + tid]       = e0;
        g_e[kk+1][b*Nn + tid + 512] = e1;
    }
}

// ---------------------------------------------------------------------------
// Row kernel: T-update. One block per (b,n) row; 128 threads x float4 = D=512.
//   FIRST: y = x/rho + log(q0*p0+eps)
//   else : y = x/rho + c          (c = log_s - z/rho, emitted by col kernel)
//   log_t = m - lse_d(y) + y ; LAST writes exp(log_t)*mask
// ---------------------------------------------------------------------------
template<bool FIRST, bool LAST>
__global__ void __launch_bounds__(128) row_kernel(
    const float* __restrict__ x, const float* __restrict__ p0,
    const float* __restrict__ q0, const float* __restrict__ mask,
    const float* __restrict__ rho, float* __restrict__ logt, int k)
{
    __shared__ float red[8];
    int row = blockIdx.x;
    int b = row >> 10;
    int tid = threadIdx.x;
    int wid = tid >> 5, lane = tid & 31;
    size_t base = (size_t)row * Dd;

    float r = __ldg(rho + k), invr = 1.f / r;
    float4 xv = ((const float4*)(x + base))[tid];
    float4 mv = ((const float4*)(g_m[k] + (size_t)b*Dd))[tid];
    float4 y;
    if (FIRST){
        float q = __ldg(q0 + row);
        float4 pv = ((const float4*)(p0 + (size_t)b*Dd))[tid];
        y.x = xv.x*invr + logf(q*pv.x + EPSc);
        y.y = xv.y*invr + logf(q*pv.y + EPSc);
        y.z = xv.z*invr + logf(q*pv.z + EPSc);
        y.w = xv.w*invr + logf(q*pv.w + EPSc);
    } else {
        float4 cv = ((const float4*)(g_c + base))[tid];
        y.x = xv.x*invr + cv.x;
        y.y = xv.y*invr + cv.y;
        y.z = xv.z*invr + cv.z;
        y.w = xv.w*invr + cv.w;
    }

    float mx = fmaxf(fmaxf(y.x, y.y), fmaxf(y.z, y.w));
    mx = warpMax(mx);
    if (lane == 0) red[wid] = mx;
    __syncthreads();
    if (wid == 0){ float u = (lane < 4) ? red[lane] : -3.4e38f; u = warpMax(u); if (lane==0) red[4]=u; }
    __syncthreads();
    mx = red[4];
    float se = expf(y.x-mx) + expf(y.y-mx) + expf(y.z-mx) + expf(y.w-mx);
    se = warpSum(se);
    if (lane == 0) red[wid] = se;
    __syncthreads();
    if (wid == 0){ float u = (lane < 4) ? red[lane] : 0.f; u = warpSum(u); if (lane==0) red[5]=u; }
    __syncthreads();
    float L = mx + logf(red[5]);

    float4 lt;
    lt.x = mv.x + y.x - L;
    lt.y = mv.y + y.y - L;
    lt.z = mv.z + y.z - L;
    lt.w = mv.w + y.w - L;
    if (LAST){
        float mk = __ldg(mask + row);
        lt.x = expf(lt.x)*mk; lt.y = expf(lt.y)*mk;
        lt.z = expf(lt.z)*mk; lt.w = expf(lt.w)*mk;
    }
    ((float4*)(logt + base))[tid] = lt;
}

// ---------------------------------------------------------------------------
// Column kernel: S-update + z-update, smem-cached (no DRAM re-read in pass 2).
// Block = (16 d-cols, one batch). 512 threads: tdx = tid&3 (float4 group),
// tn = tid>>2 (128 n-rows in flight, 8 steps over N=1024).
// Pass 1: stream logt (+z) into smem, online LSE per d-column.
// Reduce 128-way per column in smem. Pass 2: from smem, write
//   c = log_s - z'/rho[k+1]   and   z' = z + rho*(t - s)*mask.
// ---------------------------------------------------------------------------
template<bool FIRST>
__global__ void __launch_bounds__(512) col_kernel(
    const float* __restrict__ mask, const float* __restrict__ rho,
    const float* __restrict__ a1, const float* __restrict__ logt, int k)
{
    extern __shared__ __align__(16) float smem[];
    float4* s_lt = (float4*)smem;                                   // [Nn][4]
    float4* s_z  = (float4*)(smem + Nn*16);                         // [Nn][4] (!FIRST)
    float*  tail = smem + Nn*16*(FIRST ? 1 : 2);
    float*  s_e  = tail;                                            // Nn
    float*  s_mk = tail + Nn;                                       // Nn
    float*  s_rm = tail + 2*Nn;                                     // 4*512
    float*  s_rs = tail + 2*Nn + 2048;                              // 4*512

    int b = blockIdx.y;
    int tid = threadIdx.x;
    int tdx = tid & 3, tn = tid >> 2;
    int dt4 = blockIdx.x * 4;           // float4 offset of this 16-col tile

    float r   = __ldg(rho + k);
    float inv = 1.f / (__ldg(a1 + k) + r);
    float invrn = 1.f / __ldg(rho + (k+1));

    // preload eta stage + mask for this batch
    for (int i = tid; i < Nn; i += 512){
        s_e[i]  = g_e[k][b*Nn + i];
        s_mk[i] = mask[b*Nn + i];
    }

    const float4* lt4 = (const float4*)logt;
    const float4* gz4 = (const float4*)g_z;

    float mx0=-3.4e38f,mx1=-3.4e38f,mx2=-3.4e38f,mx3=-3.4e38f;
    float sm0=0.f,sm1=0.f,sm2=0.f,sm3=0.f;

#pragma unroll
    for (int s = 0; s < 8; s++){
        int n = tn + s*128;
        size_t gi = (size_t)(b*Nn + n)*(Dd/4) + dt4 + tdx;
        float4 lt = lt4[gi];
        float4 zv = FIRST ? make_float4(0.f,0.f,0.f,0.f) : gz4[gi];
        s_lt[n*4 + tdx] = lt;
        if (!FIRST) s_z[n*4 + tdx] = zv;
        float v0 = (zv.x + r*lt.x)*inv;
        float v1 = (zv.y + r*lt.y)*inv;
        float v2 = (zv.z + r*lt.z)*inv;
        float v3 = (zv.w + r*lt.w)*inv;
        if (v0 > mx0){ sm0 = sm0*expf(mx0-v0) + 1.f; mx0 = v0; } else sm0 += expf(v0-mx0);
        if (v1 > mx1){ sm1 = sm1*expf(mx1-v1) + 1.f; mx1 = v1; } else sm1 += expf(v1-mx1);
        if (v2 > mx2){ sm2 = sm2*expf(mx2-v2) + 1.f; mx2 = v2; } else sm2 += expf(v2-mx2);
        if (v3 > mx3){ sm3 = sm3*expf(mx3-v3) + 1.f; mx3 = v3; } else sm3 += expf(v3-mx3);
    }

    s_rm[0*512+tid]=mx0; s_rs[0*512+tid]=sm0;
    s_rm[1*512+tid]=mx1; s_rs[1*512+tid]=sm1;
    s_rm[2*512+tid]=mx2; s_rs[2*512+tid]=sm2;
    s_rm[3*512+tid]=mx3; s_rs[3*512+tid]=sm3;
    __syncthreads();
#pragma unroll
    for (int off = 256; off >= 4; off >>= 1){
        if (tid < off){
#pragma unroll
            for (int j = 0; j < 4; j++){
                float M  = s_rm[j*512+tid],     S  = s_rs[j*512+tid];
                float M2 = s_rm[j*512+tid+off], S2 = s_rs[j*512+tid+off];
                float nm = fmaxf(M, M2);
                s_rs[j*512+tid] = S*expf(M-nm) + S2*expf(M2-nm);
                s_rm[j*512+tid] = nm;
            }
        }
        __syncthreads();
    }
    // final LSE per own d-column group (broadcast reads)
    float L0 = s_rm[0*512+tdx] + logf(s_rs[0*512+tdx]);
    float L1 = s_rm[1*512+tdx] + logf(s_rs[1*512+tdx]);
    float L2 = s_rm[2*512+tdx] + logf(s_rs[2*512+tdx]);
    float L3 = s_rm[3*512+tdx] + logf(s_rs[3*512+tdx]);

    float4* gc4 = (float4*)g_c;
    float4* gzw4 = (float4*)g_z;

#pragma unroll
    for (int s = 0; s < 8; s++){
        int n = tn + s*128;
        size_t gi = (size_t)(b*Nn + n)*(Dd/4) + dt4 + tdx;
        float4 lt = s_lt[n*4 + tdx];
        float4 zv = FIRST ? make_float4(0.f,0.f,0.f,0.f) : s_z[n*4 + tdx];
        float e = s_e[n], mk = s_mk[n];

        float4 ls, zn, cv;
        ls.x = e - L0 + (zv.x + r*lt.x)*inv;
        ls.y = e - L1 + (zv.y + r*lt.y)*inv;
        ls.z = e - L2 + (zv.z + r*lt.z)*inv;
        ls.w = e - L3 + (zv.w + r*lt.w)*inv;
        zn.x = zv.x + r*(expf(lt.x)*mk - expf(ls.x)*mk);
        zn.y = zv.y + r*(expf(lt.y)*mk - expf(ls.y)*mk);
        zn.z = zv.z + r*(expf(lt.z)*mk - expf(ls.z)*mk);
        zn.w = zv.w + r*(expf(lt.w)*mk - expf(ls.w)*mk);
        cv.x = ls.x - zn.x*invrn;
        cv.y = ls.y - zn.y*invrn;
        cv.z = ls.z - zn.z*invrn;
        cv.w = ls.w - zn.w*invrn;
        gc4[gi]  = cv;
        gzw4[gi] = zn;
    }
}

// ---------------------------------------------------------------------------
extern "C" void kernel_launch(void* const* d_in, const int* in_sizes, int n_in,
                              void* d_out, int out_size)
{
    const float* x    = (const float*)d_in[0];
    const float* p0   = (const float*)d_in[1];
    const float* q0   = (const float*)d_in[2];
    const float* a1   = (const float*)d_in[3];
    const float* a2   = (const float*)d_in[4];
    const float* a3   = (const float*)d_in[5];
    const float* rho  = (const float*)d_in[6];
    const float* mask = (const float*)d_in[7];
    float* out = (float*)d_out;   // doubles as the log_t buffer between passes

    const int SM_FIRST = Nn*16*4 + (2*Nn + 4096)*4;   // 90112 B
    const int SM_REST  = SM_FIRST + Nn*16*4;          // 155648 B
    cudaFuncSetAttribute(col_kernel<true>,  cudaFuncAttributeMaxDynamicSharedMemorySize, SM_FIRST);
    cudaFuncSetAttribute(col_kernel<false>, cudaFuncAttributeMaxDynamicSharedMemorySize, SM_REST);

    precomp_kernel<<<Bb, 512>>>(p0, q0, a2, a3, rho);

    dim3 cgrid(Dd / 16, Bb);
    // iter 0
    row_kernel<true,  false><<<Bb*Nn, 128>>>(x, p0, q0, mask, rho, out, 0);
    col_kernel<true ><<<cgrid, 512, SM_FIRST>>>(mask, rho, a1, out, 0);
    // iter 1
    row_kernel<false, false><<<Bb*Nn, 128>>>(x, p0, q0, mask, rho, out, 1);
    col_kernel<false><<<cgrid, 512, SM_REST>>>(mask, rho, a1, out, 1);
    // iter 2
    row_kernel<false, false><<<Bb*Nn, 128>>>(x, p0, q0, mask, rho, out, 2);
    col_kernel<false><<<cgrid, 512, SM_REST>>>(mask, rho, a1, out, 2);
    // iter 3: only the T-update affects the output
    row_kernel<false, true ><<<Bb*Nn, 128>>>(x, p0, q0, mask, rho, out, 3);
}

// round 3
// speedup vs baseline: 1.4476x; 1.4476x over previous
#include <cuda_runtime.h>
#include <math.h>

#define Bb 64
#define Nn 1024
#define Dd 512
#define TOT (Bb*Nn*Dd)
#define NUMIT 4
#define EPSc 1e-8f

// Scratch (device globals — no runtime allocation allowed)
__device__ float g_z[TOT];                 // ADMM dual z (B,N,D)
__device__ float g_m[NUMIT][Bb*Dd];        // log_mu stage k
__device__ float g_e[NUMIT][Bb*Nn];        // log_eta stage k
__device__ float g_Lc[3][Bb*Dd];           // col-LSE per iteration
__device__ float g_L0row[Bb*Nn];           // row-LSE of iteration 0

__device__ __forceinline__ float warpMax(float v){
#pragma unroll
    for (int o = 16; o > 0; o >>= 1) v = fmaxf(v, __shfl_xor_sync(0xffffffffu, v, o));
    return v;
}
__device__ __forceinline__ float warpSum(float v){
#pragma unroll
    for (int o = 16; o > 0; o >>= 1) v += __shfl_xor_sync(0xffffffffu, v, o);
    return v;
}

// ---------------------------------------------------------------------------
// Precompute log_mu / log_eta trajectories (dual marginals stay separable:
// the (B,N,D)-shaped halves of z1/z2 cancel inside their logsumexps).
// ---------------------------------------------------------------------------
__global__ void __launch_bounds__(512) precomp_kernel(
    const float* __restrict__ p0, const float* __restrict__ q0,
    const float* __restrict__ a2, const float* __restrict__ a3,
    const float* __restrict__ rho)
{
    __shared__ float red[32];
    int b = blockIdx.x, tid = threadIdx.x;
    int wid = tid >> 5, lane = tid & 31;

    // ---- mu chain (D=512) ----
    float lp = logf(p0[b*Dd + tid]);
    float m = lp, A = 0.f;
    g_m[0][b*Dd + tid] = lp;
    for (int kk = 0; kk < NUMIT-1; kk++){
        float r = rho[kk], a = a2[kk];
        float g = (r*m + a*lp - A) / (r + a);
        float v = warpMax(g);
        if (lane == 0) red[wid] = v;
        __syncthreads();
        if (wid == 0){ float u = (lane < 16) ? red[lane] : -3.4e38f; u = warpMax(u); if (lane==0) red[16]=u; }
        __syncthreads();
        float mx = red[16];
        __syncthreads();
        float s = warpSum(expf(g - mx));
        if (lane == 0) red[wid] = s;
        __syncthreads();
        if (wid == 0){ float u = (lane < 16) ? red[lane] : 0.f; u = warpSum(u); if (lane==0) red[16]=u; }
        __syncthreads();
        float L = mx + logf(red[16]);
        __syncthreads();
        m = g - L;
        A += r * expf(m);
        g_m[kk+1][b*Dd + tid] = m;
    }

    // ---- eta chain (N=1024, 2 per thread) ----
    float lq0 = logf(q0[b*Nn + tid] + EPSc);
    float lq1 = logf(q0[b*Nn + tid + 512] + EPSc);
    float e0 = lq0, e1 = lq1, C0 = 0.f, C1 = 0.f;
    g_e[0][b*Nn + tid]       = e0;
    g_e[0][b*Nn + tid + 512] = e1;
    for (int kk = 0; kk < NUMIT-1; kk++){
        float r = rho[kk], a = a3[kk];
        float h0 = (r*e0 + a*lq0 - C0) / (r + a);
        float h1 = (r*e1 + a*lq1 - C1) / (r + a);
        float v = warpMax(fmaxf(h0, h1));
        if (lane == 0) red[wid] = v;
        __syncthreads();
        if (wid == 0){ float u = (lane < 16) ? red[lane] : -3.4e38f; u = warpMax(u); if (lane==0) red[16]=u; }
        __syncthreads();
        float mx = red[16];
        __syncthreads();
        float s = warpSum(expf(h0 - mx) + expf(h1 - mx));
        if (lane == 0) red[wid] = s;
        __syncthreads();
        if (wid == 0){ float u = (lane < 16) ? red[lane] : 0.f; u = warpSum(u); if (lane==0) red[16]=u; }
        __syncthreads();
        float L = mx + logf(red[16]);
        __syncthreads();
        e0 = h0 - L; e1 = h1 - L;
        C0 += r * expf(e0); C1 += r * expf(e1);
        g_e[kk+1][b*Nn + tid]       = e0;
        g_e[kk+1][b*Nn + tid + 512] = e1;
    }
}

// ---------------------------------------------------------------------------
// Block-wide logsumexp over 512 values held as one float4 per thread (128 thr).
// ---------------------------------------------------------------------------
__device__ __forceinline__ float blockLSE512(float4 y, float* red, int wid, int lane){
    float mx = fmaxf(fmaxf(y.x, y.y), fmaxf(y.z, y.w));
    mx = warpMax(mx);
    if (lane == 0) red[wid] = mx;
    __syncthreads();
    if (wid == 0){ float u = (lane < 4) ? red[lane] : -3.4e38f; u = warpMax(u); if (lane==0) red[4]=u; }
    __syncthreads();
    mx = red[4];
    float se = expf(y.x-mx) + expf(y.y-mx) + expf(y.z-mx) + expf(y.w-mx);
    se = warpSum(se);
    if (lane == 0) red[wid] = se;
    __syncthreads();
    if (wid == 0){ float u = (lane < 4) ? red[lane] : 0.f; u = warpSum(u); if (lane==0) red[5]=u; }
    __syncthreads();
    return mx + logf(red[5]);
}

// ---------------------------------------------------------------------------
// Iteration-0 row kernel: only writes the per-row LSE (B,N). lt0 itself is
// recomputed on the fly by consumers (cheap: one logf+fma per element).
//   y0 = x/rho0 + log(q0*p0 + eps);  L0row = lse_d(y0)
// ---------------------------------------------------------------------------
__global__ void __launch_bounds__(128) row0lse_kernel(
    const float* __restrict__ x, const float* __restrict__ p0,
    const float* __restrict__ q0, const float* __restrict__ rho)
{
    __shared__ float red[8];
    int row = blockIdx.x, b = row >> 10;
    int tid = threadIdx.x, wid = tid >> 5, lane = tid & 31;
    size_t base = (size_t)row * Dd;
    float invr = 1.f / __ldg(rho);
    float q = __ldg(q0 + row);
    float4 xv = ((const float4*)(x + base))[tid];
    float4 pv = ((const float4*)(p0 + (size_t)b*Dd))[tid];
    float4 y;
    y.x = xv.x*invr + logf(q*pv.x + EPSc);
    y.y = xv.y*invr + logf(q*pv.y + EPSc);
    y.z = xv.z*invr + logf(q*pv.z + EPSc);
    y.w = xv.w*invr + logf(q*pv.w + EPSc);
    float L = blockLSE512(y, red, wid, lane);
    if (tid == 0) g_L0row[row] = L;
}

// ---------------------------------------------------------------------------
// Col reduce: L_c[k][b,d] = lse_n( (z + rho*log_t)/(a1+rho) ).
// Read-only streaming; block = (b, 32 d-cols), 256 threads (8 n-rows in
// flight), batch of 4 loads per step for MLP.
// FIRST recomputes lt0 from x (z=0); else reads lt_buf and g_z.
// ---------------------------------------------------------------------------
template<bool FIRST>
__global__ void __launch_bounds__(256) colred_kernel(
    const float* __restrict__ x, const float* __restrict__ p0,
    const float* __restrict__ q0, const float* __restrict__ rho,
    const float* __restrict__ a1, const float* __restrict__ lt_buf, int k)
{
    __shared__ float s_m[256], s_s[256];
    __shared__ float s_q[Nn], s_L[Nn];     // used only when FIRST

    int b = blockIdx.y, tid = threadIdx.x;
    int dc = tid & 31, nr = tid >> 5;
    int d = blockIdx.x * 32 + dc;

    float r   = __ldg(rho + k);
    float inv = 1.f / (__ldg(a1 + k) + r);
    float invr0 = 1.f / r;
    float pd = 0.f, m0d = 0.f;
    if (FIRST){
        pd  = p0[b*Dd + d];
        m0d = g_m[0][b*Dd + d];
        for (int i = tid; i < Nn; i += 256){
            s_q[i] = q0[b*Nn + i];
            s_L[i] = g_L0row[b*Nn + i];
        }
        __syncthreads();
    }

    size_t cb = (size_t)b * Nn * Dd + d;
    float mx = -3.4e38f, sm = 0.f;
    for (int s0 = 0; s0 < Nn/8; s0 += 4){
        float vv[4];
#pragma unroll
        for (int j = 0; j < 4; j++){
            int n = nr + (s0 + j) * 8;
            size_t idx = cb + (size_t)n * Dd;
            if (FIRST){
                float xv = x[idx];
                float y0 = xv*invr0 + logf(s_q[n]*pd + EPSc);
                float lt = m0d + y0 - s_L[n];
                vv[j] = r * lt * inv;
            } else {
                vv[j] = (g_z[idx] + r * lt_buf[idx]) * inv;
            }
        }
#pragma unroll
        for (int j = 0; j < 4; j++){
            float v = vv[j];
            if (v > mx){ sm = sm*expf(mx - v) + 1.f; mx = v; }
            else       { sm += expf(v - mx); }
        }
    }
    s_m[tid] = mx; s_s[tid] = sm;
    __syncthreads();
    if (tid < 32){
        float M = s_m[tid], S = s_s[tid];
#pragma unroll
        for (int j = 1; j < 8; j++){
            float M2 = s_m[j*32 + tid], S2 = s_s[j*32 + tid];
            float nm = fmaxf(M, M2);
            S = S*expf(M - nm) + S2*expf(M2 - nm);
            M = nm;
        }
        g_Lc[k][b*Dd + blockIdx.x*32 + tid] = M + logf(S);
    }
}

// ---------------------------------------------------------------------------
// Fused kernel: col-k finalize + row-(k+1) update, block per (b,n) row.
//   v  = (z + r*lt)/(a1+r);  ls = e - Lc + v
//   z' = z + r*(exp(lt) - exp(ls))*mask
//   y  = x/r' + ls - z'/r';  lt' = m' + y - lse_d(y)
// MODE 0: z=0 and lt recomputed from x (iteration 0); writes z', lt'.
// MODE 1: reads lt,z; writes z', lt'.
// MODE 2: reads lt,z; writes final exp(lt')*mask only.
// ---------------------------------------------------------------------------
template<int MODE>
__global__ void __launch_bounds__(128) fused_kernel(
    const float* __restrict__ x, const float* __restrict__ p0,
    const float* __restrict__ q0, const float* __restrict__ mask,
    const float* __restrict__ rho, const float* __restrict__ a1,
    float* lt_buf, int k)
{
    __shared__ float red[8];
    int row = blockIdx.x, b = row >> 10;
    int tid = threadIdx.x, wid = tid >> 5, lane = tid & 31;
    size_t base = (size_t)row * Dd;

    float r     = __ldg(rho + k);
    float inv   = 1.f / (__ldg(a1 + k) + r);
    float invrn = 1.f / __ldg(rho + k + 1);
    float e  = g_e[k][row];
    float mk = __ldg(mask + row);

    float4 xv = ((const float4*)(x + base))[tid];
    float4 Lc = ((const float4*)(g_Lc[k]  + (size_t)b*Dd))[tid];
    float4 mn = ((const float4*)(g_m[k+1] + (size_t)b*Dd))[tid];

    float4 lt, zv;
    if (MODE == 0){
        float q    = __ldg(q0 + row);
        float L0r  = g_L0row[row];
        float invr0 = 1.f / r;
        float4 pv = ((const float4*)(p0 + (size_t)b*Dd))[tid];
        float4 m0 = ((const float4*)(g_m[0] + (size_t)b*Dd))[tid];
        lt.x = m0.x + xv.x*invr0 + logf(q*pv.x + EPSc) - L0r;
        lt.y = m0.y + xv.y*invr0 + logf(q*pv.y + EPSc) - L0r;
        lt.z = m0.z + xv.z*invr0 + logf(q*pv.z + EPSc) - L0r;
        lt.w = m0.w + xv.w*invr0 + logf(q*pv.w + EPSc) - L0r;
        zv = make_float4(0.f, 0.f, 0.f, 0.f);
    } else {
        lt = ((const float4*)(lt_buf + base))[tid];
        zv = ((const float4*)(g_z + base))[tid];
    }

    float4 y, zn;
    {
        float v, ls;
        v = (zv.x + r*lt.x)*inv; ls = e - Lc.x + v;
        zn.x = zv.x + r*(expf(lt.x) - expf(ls))*mk;
        y.x  = xv.x*invrn + ls - zn.x*invrn;
        v = (zv.y + r*lt.y)*inv; ls = e - Lc.y + v;
        zn.y = zv.y + r*(expf(lt.y) - expf(ls))*mk;
        y.y  = xv.y*invrn + ls - zn.y*invrn;
        v = (zv.z + r*lt.z)*inv; ls = e - Lc.z + v;
        zn.z = zv.z + r*(expf(lt.z) - expf(ls))*mk;
        y.z  = xv.z*invrn + ls - zn.z*invrn;
        v = (zv.w + r*lt.w)*inv; ls = e - Lc.w + v;
        zn.w = zv.w + r*(expf(lt.w) - expf(ls))*mk;
        y.w  = xv.w*invrn + ls - zn.w*invrn;
    }

    float L = blockLSE512(y, red, wid, lane);

    float4 o;
    o.x = mn.x + y.x - L;
    o.y = mn.y + y.y - L;
    o.z = mn.z + y.z - L;
    o.w = mn.w + y.w - L;
    if (MODE == 2){
        o.x = expf(o.x)*mk; o.y = expf(o.y)*mk;
        o.z = expf(o.z)*mk; o.w = expf(o.w)*mk;
    } else {
        ((float4*)(g_z + base))[tid] = zn;
    }
    ((float4*)(lt_buf + base))[tid] = o;
}

// ---------------------------------------------------------------------------
extern "C" void kernel_launch(void* const* d_in, const int* in_sizes, int n_in,
                              void* d_out, int out_size)
{
    const float* x    = (const float*)d_in[0];
    const float* p0   = (const float*)d_in[1];
    const float* q0   = (const float*)d_in[2];
    const float* a1   = (const float*)d_in[3];
    const float* a2   = (const float*)d_in[4];
    const float* a3   = (const float*)d_in[5];
    const float* rho  = (const float*)d_in[6];
    const float* mask = (const float*)d_in[7];
    float* out = (float*)d_out;   // doubles as the log_t buffer between passes

    precomp_kernel<<<Bb, 512>>>(p0, q0, a2, a3, rho);

    dim3 cgrid(Dd / 32, Bb);
    row0lse_kernel<<<Bb*Nn, 128>>>(x, p0, q0, rho);

    colred_kernel<true ><<<cgrid, 256>>>(x, p0, q0, rho, a1, out, 0);
    fused_kernel<0><<<Bb*Nn, 128>>>(x, p0, q0, mask, rho, a1, out, 0);

    colred_kernel<false><<<cgrid, 256>>>(x, p0, q0, rho, a1, out, 1);
    fused_kernel<1><<<Bb*Nn, 128>>>(x, p0, q0, mask, rho, a1, out, 1);

    colred_kernel<false><<<cgrid, 256>>>(x, p0, q0, rho, a1, out, 2);
    fused_kernel<2><<<Bb*Nn, 128>>>(x, p0, q0, mask, rho, a1, out, 2);
}

// round 4
// speedup vs baseline: 1.7906x; 1.2369x over previous
#include <cuda_runtime.h>
#include <math.h>

#define Bb 64
#define Nn 1024
#define Dd 512
#define TOT (Bb*Nn*Dd)
#define NUMIT 4
#define EPSc 1e-8f

// Scratch (device globals — no runtime allocation allowed)
__device__ float g_u[TOT];                 // u_k = (z_k + rho_k*lt_k)/(a1_k+rho_k)
__device__ float g_m[NUMIT][Bb*Dd];        // log_mu stage k
__device__ float g_e[NUMIT][Bb*Nn];        // log_eta stage k
__device__ float g_Lc[3][Bb*Dd];           // col-LSE per iteration
__device__ float g_L0row[Bb*Nn];           // row-LSE of iteration 0

__device__ __forceinline__ float warpMax(float v){
#pragma unroll
    for (int o = 16; o > 0; o >>= 1) v = fmaxf(v, __shfl_xor_sync(0xffffffffu, v, o));
    return v;
}
__device__ __forceinline__ float warpSum(float v){
#pragma unroll
    for (int o = 16; o > 0; o >>= 1) v += __shfl_xor_sync(0xffffffffu, v, o);
    return v;
}

// ---------------------------------------------------------------------------
// Precompute log_mu / log_eta trajectories (dual marginals stay separable).
// Tiny kernel: keep accurate expf/logf here.
// ---------------------------------------------------------------------------
__global__ void __launch_bounds__(512) precomp_kernel(
    const float* __restrict__ p0, const float* __restrict__ q0,
    const float* __restrict__ a2, const float* __restrict__ a3,
    const float* __restrict__ rho)
{
    __shared__ float red[32];
    int b = blockIdx.x, tid = threadIdx.x;
    int wid = tid >> 5, lane = tid & 31;

    float lp = logf(p0[b*Dd + tid]);
    float m = lp, A = 0.f;
    g_m[0][b*Dd + tid] = lp;
    for (int kk = 0; kk < NUMIT-1; kk++){
        float r = rho[kk], a = a2[kk];
        float g = (r*m + a*lp - A) / (r + a);
        float v = warpMax(g);
        if (lane == 0) red[wid] = v;
        __syncthreads();
        if (wid == 0){ float u = (lane < 16) ? red[lane] : -3.4e38f; u = warpMax(u); if (lane==0) red[16]=u; }
        __syncthreads();
        float mx = red[16];
        __syncthreads();
        float s = warpSum(expf(g - mx));
        if (lane == 0) red[wid] = s;
        __syncthreads();
        if (wid == 0){ float u = (lane < 16) ? red[lane] : 0.f; u = warpSum(u); if (lane==0) red[16]=u; }
        __syncthreads();
        float L = mx + logf(red[16]);
        __syncthreads();
        m = g - L;
        A += r * expf(m);
        g_m[kk+1][b*Dd + tid] = m;
    }

    float lq0 = logf(q0[b*Nn + tid] + EPSc);
    float lq1 = logf(q0[b*Nn + tid + 512] + EPSc);
    float e0 = lq0, e1 = lq1, C0 = 0.f, C1 = 0.f;
    g_e[0][b*Nn + tid]       = e0;
    g_e[0][b*Nn + tid + 512] = e1;
    for (int kk = 0; kk < NUMIT-1; kk++){
        float r = rho[kk], a = a3[kk];
        float h0 = (r*e0 + a*lq0 - C0) / (r + a);
        float h1 = (r*e1 + a*lq1 - C1) / (r + a);
        float v = warpMax(fmaxf(h0, h1));
        if (lane == 0) red[wid] = v;
        __syncthreads();
        if (wid == 0){ float u = (lane < 16) ? red[lane] : -3.4e38f; u = warpMax(u); if (lane==0) red[16]=u; }
        __syncthreads();
        float mx = red[16];
        __syncthreads();
        float s = warpSum(expf(h0 - mx) + expf(h1 - mx));
        if (lane == 0) red[wid] = s;
        __syncthreads();
        if (wid == 0){ float u = (lane < 16) ? red[lane] : 0.f; u = warpSum(u); if (lane==0) red[16]=u; }
        __syncthreads();
        float L = mx + logf(red[16]);
        __syncthreads();
        e0 = h0 - L; e1 = h1 - L;
        C0 += r * expf(e0); C1 += r * expf(e1);
        g_e[kk+1][b*Nn + tid]       = e0;
        g_e[kk+1][b*Nn + tid + 512] = e1;
    }
}

// ---------------------------------------------------------------------------
// Block logsumexp over 512 values (one float4 per thread, 128 threads).
// ---------------------------------------------------------------------------
__device__ __forceinline__ float blockLSE512(float4 y, float* red, int wid, int lane){
    float mx = fmaxf(fmaxf(y.x, y.y), fmaxf(y.z, y.w));
    mx = warpMax(mx);
    if (lane == 0) red[wid] = mx;
    __syncthreads();
    if (wid == 0){ float u = (lane < 4) ? red[lane] : -3.4e38f; u = warpMax(u); if (lane==0) red[4]=u; }
    __syncthreads();
    mx = red[4];
    float se = __expf(y.x-mx) + __expf(y.y-mx) + __expf(y.z-mx) + __expf(y.w-mx);
    se = warpSum(se);
    if (lane == 0) red[wid] = se;
    __syncthreads();
    if (wid == 0){ float u = (lane < 4) ? red[lane] : 0.f; u = warpSum(u); if (lane==0) red[5]=u; }
    __syncthreads();
    return mx + __logf(red[5]);
}

// ---------------------------------------------------------------------------
// Iteration-0 row LSE: L0row = lse_d( x/rho0 + log(q0*p0+eps) ).
// ---------------------------------------------------------------------------
__global__ void __launch_bounds__(128) row0lse_kernel(
    const float* __restrict__ x, const float* __restrict__ p0,
    const float* __restrict__ q0, const float* __restrict__ rho)
{
    __shared__ float red[8];
    int row = blockIdx.x, b = row >> 10;
    int tid = threadIdx.x, wid = tid >> 5, lane = tid & 31;
    size_t base = (size_t)row * Dd;
    float invr = 1.f / __ldg(rho);
    float q = __ldg(q0 + row);
    float4 xv = ((const float4*)(x + base))[tid];
    float4 pv = ((const float4*)(p0 + (size_t)b*Dd))[tid];
    float4 y;
    y.x = xv.x*invr + __logf(q*pv.x + EPSc);
    y.y = xv.y*invr + __logf(q*pv.y + EPSc);
    y.z = xv.z*invr + __logf(q*pv.z + EPSc);
    y.w = xv.w*invr + __logf(q*pv.w + EPSc);
    float L = blockLSE512(y, red, wid, lane);
    if (tid == 0) g_L0row[row] = L;
}

// ---------------------------------------------------------------------------
// Col reduce, iteration 0: recompute lt0 from x; v0 = rho0*lt0/(a1+rho0).
// ---------------------------------------------------------------------------
__global__ void __launch_bounds__(256) colred0_kernel(
    const float* __restrict__ x, const float* __restrict__ p0,
    const float* __restrict__ q0, const float* __restrict__ rho,
    const float* __restrict__ a1)
{
    __shared__ float s_m[256], s_s[256];
    __shared__ float s_q[Nn], s_L[Nn];

    int b = blockIdx.y, tid = threadIdx.x;
    int dc = tid & 31, nr = tid >> 5;
    int d = blockIdx.x * 32 + dc;

    float r   = __ldg(rho);
    float inv = 1.f / (__ldg(a1) + r);
    float invr0 = 1.f / r;
    float pd  = p0[b*Dd + d];
    float m0d = g_m[0][b*Dd + d];
    for (int i = tid; i < Nn; i += 256){
        s_q[i] = q0[b*Nn + i];
        s_L[i] = g_L0row[b*Nn + i];
    }
    __syncthreads();

    size_t cb = (size_t)b * Nn * Dd + d;
    float mx = -3.4e38f, sm = 0.f;
    for (int s0 = 0; s0 < Nn/8; s0 += 4){
        float vv[4];
#pragma unroll
        for (int j = 0; j < 4; j++){
            int n = nr + (s0 + j) * 8;
            float xv = x[cb + (size_t)n * Dd];
            float lt = m0d + xv*invr0 + __logf(s_q[n]*pd + EPSc) - s_L[n];
            vv[j] = r * lt * inv;
        }
#pragma unroll
        for (int j = 0; j < 4; j++){
            float v = vv[j];
            if (v > mx){ sm = sm*__expf(mx - v) + 1.f; mx = v; }
            else       { sm += __expf(v - mx); }
        }
    }
    s_m[tid] = mx; s_s[tid] = sm;
    __syncthreads();
    if (tid < 32){
        float M = s_m[tid], S = s_s[tid];
#pragma unroll
        for (int j = 1; j < 8; j++){
            float M2 = s_m[j*32 + tid], S2 = s_s[j*32 + tid];
            float nm = fmaxf(M, M2);
            S = S*__expf(M - nm) + S2*__expf(M2 - nm);
            M = nm;
        }
        g_Lc[0][b*Dd + blockIdx.x*32 + tid] = M + __logf(S);
    }
}

// ---------------------------------------------------------------------------
// Col reduce, k>=1: v = g_u directly (already scaled). Single-array stream.
// ---------------------------------------------------------------------------
__global__ void __launch_bounds__(256) colredU_kernel(int k)
{
    __shared__ float s_m[256], s_s[256];
    int b = blockIdx.y, tid = threadIdx.x;
    int dc = tid & 31, nr = tid >> 5;
    int d = blockIdx.x * 32 + dc;

    size_t cb = (size_t)b * Nn * Dd + d;
    float mx = -3.4e38f, sm = 0.f;
    for (int s0 = 0; s0 < Nn/8; s0 += 4){
        float vv[4];
#pragma unroll
        for (int j = 0; j < 4; j++){
            int n = nr + (s0 + j) * 8;
            vv[j] = g_u[cb + (size_t)n * Dd];
        }
#pragma unroll
        for (int j = 0; j < 4; j++){
            float v = vv[j];
            if (v > mx){ sm = sm*__expf(mx - v) + 1.f; mx = v; }
            else       { sm += __expf(v - mx); }
        }
    }
    s_m[tid] = mx; s_s[tid] = sm;
    __syncthreads();
    if (tid < 32){
        float M = s_m[tid], S = s_s[tid];
#pragma unroll
        for (int j = 1; j < 8; j++){
            float M2 = s_m[j*32 + tid], S2 = s_s[j*32 + tid];
            float nm = fmaxf(M, M2);
            S = S*__expf(M - nm) + S2*__expf(M2 - nm);
            M = nm;
        }
        g_Lc[k][b*Dd + blockIdx.x*32 + tid] = M + __logf(S);
    }
}

// ---------------------------------------------------------------------------
// Fused: col-k finalize + row-(k+1) update. Block per (b,n) row.
// MODE 0: lt0 recomputed from x (z=0). MODE 1: reads lt,u; writes lt',u'.
// MODE 2: reads lt,u; writes final exp(lt')*mask.
//   z   = u*(a1+r) - r*lt        (MODE>=1)
//   ls  = e - Lc + u ;  z' = z + r*(exp(lt)-exp(ls))*mask
//   y   = (x - z')/r' + ls ;  lt' = m' + y - lse_d(y)
//   u'  = (z' + r'*lt')/(a1' + r')
// ---------------------------------------------------------------------------
template<int MODE>
__global__ void __launch_bounds__(128) fused_kernel(
    const float* __restrict__ x, const float* __restrict__ p0,
    const float* __restrict__ q0, const float* __restrict__ mask,
    const float* __restrict__ rho, const float* __restrict__ a1,
    float* lt_buf, int k)
{
    __shared__ float red[8];
    int row = blockIdx.x, b = row >> 10;
    int tid = threadIdx.x, wid = tid >> 5, lane = tid & 31;
    size_t base = (size_t)row * Dd;

    float r     = __ldg(rho + k);
    float sfac  = __ldg(a1 + k) + r;          // a1_k + rho_k
    float inv   = 1.f / sfac;
    float rn    = __ldg(rho + k + 1);
    float invrn = 1.f / rn;
    float invsn = (MODE == 2) ? 0.f : 1.f / (__ldg(a1 + k + 1) + rn);
    float e  = g_e[k][row];
    float mk = __ldg(mask + row);

    float4 xv = ((const float4*)(x + base))[tid];
    float4 Lc = ((const float4*)(g_Lc[k]  + (size_t)b*Dd))[tid];
    float4 mn = ((const float4*)(g_m[k+1] + (size_t)b*Dd))[tid];

    float4 lt, uv;
    if (MODE == 0){
        float q     = __ldg(q0 + row);
        float L0r   = g_L0row[row];
        float invr0 = 1.f / r;
        float4 pv = ((const float4*)(p0 + (size_t)b*Dd))[tid];
        float4 m0 = ((const float4*)(g_m[0] + (size_t)b*Dd))[tid];
        lt.x = m0.x + xv.x*invr0 + __logf(q*pv.x + EPSc) - L0r;
        lt.y = m0.y + xv.y*invr0 + __logf(q*pv.y + EPSc) - L0r;
        lt.z = m0.z + xv.z*invr0 + __logf(q*pv.z + EPSc) - L0r;
        lt.w = m0.w + xv.w*invr0 + __logf(q*pv.w + EPSc) - L0r;
        uv.x = r*lt.x*inv; uv.y = r*lt.y*inv;
        uv.z = r*lt.z*inv; uv.w = r*lt.w*inv;
    } else {
        lt = ((const float4*)(lt_buf + base))[tid];
        uv = ((const float4*)(g_u + base))[tid];
    }

    float4 y, zn;
    {
        float z, ls;
        z = (MODE == 0) ? 0.f : uv.x*sfac - r*lt.x;
        ls = e - Lc.x + uv.x;
        zn.x = z + r*(__expf(lt.x) - __expf(ls))*mk;
        y.x  = (xv.x - zn.x)*invrn + ls;
        z = (MODE == 0) ? 0.f : uv.y*sfac - r*lt.y;
        ls = e - Lc.y + uv.y;
        zn.y = z + r*(__expf(lt.y) - __expf(ls))*mk;
        y.y  = (xv.y - zn.y)*invrn + ls;
        z = (MODE == 0) ? 0.f : uv.z*sfac - r*lt.z;
        ls = e - Lc.z + uv.z;
        zn.z = z + r*(__expf(lt.z) - __expf(ls))*mk;
        y.z  = (xv.z - zn.z)*invrn + ls;
        z = (MODE == 0) ? 0.f : uv.w*sfac - r*lt.w;
        ls = e - Lc.w + uv.w;
        zn.w = z + r*(__expf(lt.w) - __expf(ls))*mk;
        y.w  = (xv.w - zn.w)*invrn + ls;
    }

    float L = blockLSE512(y, red, wid, lane);

    float4 o;
    o.x = mn.x + y.x - L;
    o.y = mn.y + y.y - L;
    o.z = mn.z + y.z - L;
    o.w = mn.w + y.w - L;
    if (MODE == 2){
        o.x = __expf(o.x)*mk; o.y = __expf(o.y)*mk;
        o.z = __expf(o.z)*mk; o.w = __expf(o.w)*mk;
    } else {
        float4 un;
        un.x = (zn.x + rn*o.x)*invsn;
        un.y = (zn.y + rn*o.y)*invsn;
        un.z = (zn.z + rn*o.z)*invsn;
        un.w = (zn.w + rn*o.w)*invsn;
        ((float4*)(g_u + base))[tid] = un;
    }
    ((float4*)(lt_buf + base))[tid] = o;
}

// ---------------------------------------------------------------------------
extern "C" void kernel_launch(void* const* d_in, const int* in_sizes, int n_in,
                              void* d_out, int out_size)
{
    const float* x    = (const float*)d_in[0];
    const float* p0   = (const float*)d_in[1];
    const float* q0   = (const float*)d_in[2];
    const float* a1   = (const float*)d_in[3];
    const float* a2   = (const float*)d_in[4];
    const float* a3   = (const float*)d_in[5];
    const float* rho  = (const float*)d_in[6];
    const float* mask = (const float*)d_in[7];
    float* out = (float*)d_out;   // doubles as the log_t buffer between passes

    precomp_kernel<<<Bb, 512>>>(p0, q0, a2, a3, rho);

    dim3 cgrid(Dd / 32, Bb);
    row0lse_kernel<<<Bb*Nn, 128>>>(x, p0, q0, rho);

    colred0_kernel<<<cgrid, 256>>>(x, p0, q0, rho, a1);
    fused_kernel<0><<<Bb*Nn, 128>>>(x, p0, q0, mask, rho, a1, out, 0);

    colredU_kernel<<<cgrid, 256>>>(1);
    fused_kernel<1><<<Bb*Nn, 128>>>(x, p0, q0, mask, rho, a1, out, 1);

    colredU_kernel<<<cgrid, 256>>>(2);
    fused_kernel<2><<<Bb*Nn, 128>>>(x, p0, q0, mask, rho, a1, out, 2);
}

// round 5
// speedup vs baseline: 1.7992x; 1.0048x over previous
#include <cuda_runtime.h>
#include <math.h>

#define Bb 64
#define Nn 1024
#define Dd 512
#define TOT (Bb*Nn*Dd)
#define NUMIT 4
#define EPSc 1e-8f

// Scratch (device globals — no runtime allocation allowed)
__device__ float g_u[TOT];                 // u_k = (z_k + rho_k*lt_k)/(a1_k+rho_k)
__device__ float g_m[NUMIT][Bb*Dd];        // log_mu stage k
__device__ float g_e[NUMIT][Bb*Nn];        // log_eta stage k
__device__ float g_Lc[3][Bb*Dd];           // col-LSE per iteration
__device__ float g_L0row[Bb*Nn];           // row-LSE of iteration 0

__device__ __forceinline__ float warpMax(float v){
#pragma unroll
    for (int o = 16; o > 0; o >>= 1) v = fmaxf(v, __shfl_xor_sync(0xffffffffu, v, o));
    return v;
}
__device__ __forceinline__ float warpSum(float v){
#pragma unroll
    for (int o = 16; o > 0; o >>= 1) v += __shfl_xor_sync(0xffffffffu, v, o);
    return v;
}

// ---------------------------------------------------------------------------
// Precompute log_mu / log_eta trajectories (dual marginals stay separable).
// ---------------------------------------------------------------------------
__global__ void __launch_bounds__(512) precomp_kernel(
    const float* __restrict__ p0, const float* __restrict__ q0,
    const float* __restrict__ a2, const float* __restrict__ a3,
    const float* __restrict__ rho)
{
    __shared__ float red[32];
    int b = blockIdx.x, tid = threadIdx.x;
    int wid = tid >> 5, lane = tid & 31;

    float lp = logf(p0[b*Dd + tid]);
    float m = lp, A = 0.f;
    g_m[0][b*Dd + tid] = lp;
    for (int kk = 0; kk < NUMIT-1; kk++){
        float r = rho[kk], a = a2[kk];
        float g = (r*m + a*lp - A) / (r + a);
        float v = warpMax(g);
        if (lane == 0) red[wid] = v;
        __syncthreads();
        if (wid == 0){ float u = (lane < 16) ? red[lane] : -3.4e38f; u = warpMax(u); if (lane==0) red[16]=u; }
        __syncthreads();
        float mx = red[16];
        __syncthreads();
        float s = warpSum(expf(g - mx));
        if (lane == 0) red[wid] = s;
        __syncthreads();
        if (wid == 0){ float u = (lane < 16) ? red[lane] : 0.f; u = warpSum(u); if (lane==0) red[16]=u; }
        __syncthreads();
        float L = mx + logf(red[16]);
        __syncthreads();
        m = g - L;
        A += r * expf(m);
        g_m[kk+1][b*Dd + tid] = m;
    }

    float lq0 = logf(q0[b*Nn + tid] + EPSc);
    float lq1 = logf(q0[b*Nn + tid + 512] + EPSc);
    float e0 = lq0, e1 = lq1, C0 = 0.f, C1 = 0.f;
    g_e[0][b*Nn + tid]       = e0;
    g_e[0][b*Nn + tid + 512] = e1;
    for (int kk = 0; kk < NUMIT-1; kk++){
        float r = rho[kk], a = a3[kk];
        float h0 = (r*e0 + a*lq0 - C0) / (r + a);
        float h1 = (r*e1 + a*lq1 - C1) / (r + a);
        float v = warpMax(fmaxf(h0, h1));
        if (lane == 0) red[wid] = v;
        __syncthreads();
        if (wid == 0){ float u = (lane < 16) ? red[lane] : -3.4e38f; u = warpMax(u); if (lane==0) red[16]=u; }
        __syncthreads();
        float mx = red[16];
        __syncthreads();
        float s = warpSum(expf(h0 - mx) + expf(h1 - mx));
        if (lane == 0) red[wid] = s;
        __syncthreads();
        if (wid == 0){ float u = (lane < 16) ? red[lane] : 0.f; u = warpSum(u); if (lane==0) red[16]=u; }
        __syncthreads();
        float L = mx + logf(red[16]);
        __syncthreads();
        e0 = h0 - L; e1 = h1 - L;
        C0 += r * expf(e0); C1 += r * expf(e1);
        g_e[kk+1][b*Nn + tid]       = e0;
        g_e[kk+1][b*Nn + tid + 512] = e1;
    }
}

// ---------------------------------------------------------------------------
// Iteration-0 row LSE, warp-per-row: L0row = lse_d( x/rho0 + log(q0*p0+eps) ).
// ---------------------------------------------------------------------------
__global__ void __launch_bounds__(256) row0lse_kernel(
    const float* __restrict__ x, const float* __restrict__ p0,
    const float* __restrict__ q0, const float* __restrict__ rho)
{
    int lane = threadIdx.x & 31;
    int row  = blockIdx.x * 8 + (threadIdx.x >> 5);
    int b = row >> 10;
    const float4* x4 = (const float4*)(x + (size_t)row * Dd);
    const float4* p4 = (const float4*)(p0 + (size_t)b * Dd);
    float invr = 1.f / __ldg(rho);
    float q = __ldg(q0 + row);

    float4 y[4];
    float mx = -3.4e38f;
#pragma unroll
    for (int i = 0; i < 4; i++){
        int c = i*32 + lane;
        float4 xv = x4[c], pv = p4[c];
        y[i].x = xv.x*invr + __logf(q*pv.x + EPSc);
        y[i].y = xv.y*invr + __logf(q*pv.y + EPSc);
        y[i].z = xv.z*invr + __logf(q*pv.z + EPSc);
        y[i].w = xv.w*invr + __logf(q*pv.w + EPSc);
        mx = fmaxf(mx, fmaxf(fmaxf(y[i].x, y[i].y), fmaxf(y[i].z, y[i].w)));
    }
    mx = warpMax(mx);
    float se = 0.f;
#pragma unroll
    for (int i = 0; i < 4; i++)
        se += __expf(y[i].x-mx) + __expf(y[i].y-mx) + __expf(y[i].z-mx) + __expf(y[i].w-mx);
    se = warpSum(se);
    if (lane == 0) g_L0row[row] = mx + __logf(se);
}

// ---------------------------------------------------------------------------
// Col reduce, iteration 0: recompute lt0 from x.
// ---------------------------------------------------------------------------
__global__ void __launch_bounds__(256) colred0_kernel(
    const float* __restrict__ x, const float* __restrict__ p0,
    const float* __restrict__ q0, const float* __restrict__ rho,
    const float* __restrict__ a1)
{
    __shared__ float s_m[256], s_s[256];
    __shared__ float s_q[Nn], s_L[Nn];

    int b = blockIdx.y, tid = threadIdx.x;
    int dc = tid & 31, nr = tid >> 5;
    int d = blockIdx.x * 32 + dc;

    float r   = __ldg(rho);
    float inv = 1.f / (__ldg(a1) + r);
    float invr0 = 1.f / r;
    float pd  = p0[b*Dd + d];
    float m0d = g_m[0][b*Dd + d];
    for (int i = tid; i < Nn; i += 256){
        s_q[i] = q0[b*Nn + i];
        s_L[i] = g_L0row[b*Nn + i];
    }
    __syncthreads();

    size_t cb = (size_t)b * Nn * Dd + d;
    float mx = -3.4e38f, sm = 0.f;
    for (int s0 = 0; s0 < Nn/8; s0 += 4){
        float vv[4];
#pragma unroll
        for (int j = 0; j < 4; j++){
            int n = nr + (s0 + j) * 8;
            float xv = x[cb + (size_t)n * Dd];
            float lt = m0d + xv*invr0 + __logf(s_q[n]*pd + EPSc) - s_L[n];
            vv[j] = r * lt * inv;
        }
#pragma unroll
        for (int j = 0; j < 4; j++){
            float v = vv[j];
            if (v > mx){ sm = sm*__expf(mx - v) + 1.f; mx = v; }
            else       { sm += __expf(v - mx); }
        }
    }
    s_m[tid] = mx; s_s[tid] = sm;
    __syncthreads();
    if (tid < 32){
        float M = s_m[tid], S = s_s[tid];
#pragma unroll
        for (int j = 1; j < 8; j++){
            float M2 = s_m[j*32 + tid], S2 = s_s[j*32 + tid];
            float nm = fmaxf(M, M2);
            S = S*__expf(M - nm) + S2*__expf(M2 - nm);
            M = nm;
        }
        g_Lc[0][b*Dd + blockIdx.x*32 + tid] = M + __logf(S);
    }
}

// ---------------------------------------------------------------------------
// Col reduce, k>=1: v = g_u directly.
// ---------------------------------------------------------------------------
__global__ void __launch_bounds__(256) colredU_kernel(int k)
{
    __shared__ float s_m[256], s_s[256];
    int b = blockIdx.y, tid = threadIdx.x;
    int dc = tid & 31, nr = tid >> 5;
    int d = blockIdx.x * 32 + dc;

    size_t cb = (size_t)b * Nn * Dd + d;
    float mx = -3.4e38f, sm = 0.f;
    for (int s0 = 0; s0 < Nn/8; s0 += 4){
        float vv[4];
#pragma unroll
        for (int j = 0; j < 4; j++){
            int n = nr + (s0 + j) * 8;
            vv[j] = g_u[cb + (size_t)n * Dd];
        }
#pragma unroll
        for (int j = 0; j < 4; j++){
            float v = vv[j];
            if (v > mx){ sm = sm*__expf(mx - v) + 1.f; mx = v; }
            else       { sm += __expf(v - mx); }
        }
    }
    s_m[tid] = mx; s_s[tid] = sm;
    __syncthreads();
    if (tid < 32){
        float M = s_m[tid], S = s_s[tid];
#pragma unroll
        for (int j = 1; j < 8; j++){
            float M2 = s_m[j*32 + tid], S2 = s_s[j*32 + tid];
            float nm = fmaxf(M, M2);
            S = S*__expf(M - nm) + S2*__expf(M2 - nm);
            M = nm;
        }
        g_Lc[k][b*Dd + blockIdx.x*32 + tid] = M + __logf(S);
    }
}

// ---------------------------------------------------------------------------
// Fused (warp-per-row): col-k finalize + row-(k+1) update.
// Each warp owns one (b,n) row: 16 elements/lane, LSE via shuffles only.
// MODE 0: lt0 recomputed from x (z=0). MODE 1: rd lt,u; wr lt',u'.
// MODE 2: rd lt,u; wr final exp(lt')*mask.
// ---------------------------------------------------------------------------
template<int MODE>
__global__ void __launch_bounds__(256) fused_kernel(
    const float* __restrict__ x, const float* __restrict__ p0,
    const float* __restrict__ q0, const float* __restrict__ mask,
    const float* __restrict__ rho, const float* __restrict__ a1,
    float* __restrict__ lt_buf, int k)
{
    int lane = threadIdx.x & 31;
    int row  = blockIdx.x * 8 + (threadIdx.x >> 5);
    int b = row >> 10;
    size_t base = (size_t)row * Dd;

    float r     = __ldg(rho + k);
    float sfac  = __ldg(a1 + k) + r;
    float inv   = 1.f / sfac;
    float rn    = __ldg(rho + k + 1);
    float invrn = 1.f / rn;
    float invsn = (MODE == 2) ? 0.f : 1.f / (__ldg(a1 + k + 1) + rn);
    float e  = g_e[k][row];
    float mk = __ldg(mask + row);

    const float4* x4  = (const float4*)(x + base);
    const float4* Lc4 = (const float4*)(g_Lc[k]  + (size_t)b*Dd);
    const float4* mn4 = (const float4*)(g_m[k+1] + (size_t)b*Dd);
    const float4* lt4 = (const float4*)(lt_buf + base);
    const float4* u4  = (const float4*)(g_u + base);

    float4 y[4], zn[4];
    float mx = -3.4e38f;
#pragma unroll
    for (int i = 0; i < 4; i++){
        int c = i*32 + lane;
        float4 xv = x4[c];
        float4 Lc = Lc4[c];
        float4 lt, uv;
        if (MODE == 0){
            float q     = __ldg(q0 + row);
            float L0r   = g_L0row[row];
            float invr0 = 1.f / r;
            float4 pv = ((const float4*)(p0 + (size_t)b*Dd))[c];
            float4 m0 = ((const float4*)(g_m[0] + (size_t)b*Dd))[c];
            lt.x = m0.x + xv.x*invr0 + __logf(q*pv.x + EPSc) - L0r;
            lt.y = m0.y + xv.y*invr0 + __logf(q*pv.y + EPSc) - L0r;
            lt.z = m0.z + xv.z*invr0 + __logf(q*pv.z + EPSc) - L0r;
            lt.w = m0.w + xv.w*invr0 + __logf(q*pv.w + EPSc) - L0r;
            uv.x = r*lt.x*inv; uv.y = r*lt.y*inv;
            uv.z = r*lt.z*inv; uv.w = r*lt.w*inv;
        } else {
            lt = lt4[c];
            uv = u4[c];
        }
        float z, ls;
        z = (MODE == 0) ? 0.f : uv.x*sfac - r*lt.x;
        ls = e - Lc.x + uv.x;
        zn[i].x = z + r*(__expf(lt.x) - __expf(ls))*mk;
        y[i].x  = (xv.x - zn[i].x)*invrn + ls;
        z = (MODE == 0) ? 0.f : uv.y*sfac - r*lt.y;
        ls = e - Lc.y + uv.y;
        zn[i].y = z + r*(__expf(lt.y) - __expf(ls))*mk;
        y[i].y  = (xv.y - zn[i].y)*invrn + ls;
        z = (MODE == 0) ? 0.f : uv.z*sfac - r*lt.z;
        ls = e - Lc.z + uv.z;
        zn[i].z = z + r*(__expf(lt.z) - __expf(ls))*mk;
        y[i].z  = (xv.z - zn[i].z)*invrn + ls;
        z = (MODE == 0) ? 0.f : uv.w*sfac - r*lt.w;
        ls = e - Lc.w + uv.w;
        zn[i].w = z + r*(__expf(lt.w) - __expf(ls))*mk;
        y[i].w  = (xv.w - zn[i].w)*invrn + ls;
        mx = fmaxf(mx, fmaxf(fmaxf(y[i].x, y[i].y), fmaxf(y[i].z, y[i].w)));
    }

    mx = warpMax(mx);
    float se = 0.f;
#pragma unroll
    for (int i = 0; i < 4; i++)
        se += __expf(y[i].x-mx) + __expf(y[i].y-mx) + __expf(y[i].z-mx) + __expf(y[i].w-mx);
    se = warpSum(se);
    float L = mx + __logf(se);

#pragma unroll
    for (int i = 0; i < 4; i++){
        int c = i*32 + lane;
        float4 mn = mn4[c];
        float4 o;
        o.x = mn.x + y[i].x - L;
        o.y = mn.y + y[i].y - L;
        o.z = mn.z + y[i].z - L;
        o.w = mn.w + y[i].w - L;
        if (MODE == 2){
            o.x = __expf(o.x)*mk; o.y = __expf(o.y)*mk;
            o.z = __expf(o.z)*mk; o.w = __expf(o.w)*mk;
        } else {
            float4 un;
            un.x = (zn[i].x + rn*o.x)*invsn;
            un.y = (zn[i].y + rn*o.y)*invsn;
            un.z = (zn[i].z + rn*o.z)*invsn;
            un.w = (zn[i].w + rn*o.w)*invsn;
            ((float4*)(g_u + base))[c] = un;
        }
        ((float4*)(lt_buf + base))[c] = o;
    }
}

// ---------------------------------------------------------------------------
extern "C" void kernel_launch(void* const* d_in, const int* in_sizes, int n_in,
                              void* d_out, int out_size)
{
    const float* x    = (const float*)d_in[0];
    const float* p0   = (const float*)d_in[1];
    const float* q0   = (const float*)d_in[2];
    const float* a1   = (const float*)d_in[3];
    const float* a2   = (const float*)d_in[4];
    const float* a3   = (const float*)d_in[5];
    const float* rho  = (const float*)d_in[6];
    const float* mask = (const float*)d_in[7];
    float* out = (float*)d_out;   // doubles as the log_t buffer between passes

    precomp_kernel<<<Bb, 512>>>(p0, q0, a2, a3, rho);

    dim3 cgrid(Dd / 32, Bb);
    row0lse_kernel<<<Bb*Nn/8, 256>>>(x, p0, q0, rho);

    colred0_kernel<<<cgrid, 256>>>(x, p0, q0, rho, a1);
    fused_kernel<0><<<Bb*Nn/8, 256>>>(x, p0, q0, mask, rho, a1, out, 0);

    colredU_kernel<<<cgrid, 256>>>(1);
    fused_kernel<1><<<Bb*Nn/8, 256>>>(x, p0, q0, mask, rho, a1, out, 1);

    colredU_kernel<<<cgrid, 256>>>(2);
    fused_kernel<2><<<Bb*Nn/8, 256>>>(x, p0, q0, mask, rho, a1, out, 2);
}

// round 6
// speedup vs baseline: 1.9971x; 1.1100x over previous
#include <cuda_runtime.h>
#include <math.h>

#define Bb 64
#define Nn 1024
#define Dd 512
#define TOT (Bb*Nn*Dd)
#define NUMIT 4
#define EPSc 1e-8f
#define LOG2E 1.44269504088896340736f
#define LN2f  0.69314718055994530942f

// Scratch (device globals). ALL log-domain state is stored in BASE 2:
__device__ float g_u[TOT];                 // U2 = u_k/ln2,  u_k=(z+rho*lt)/(a1+rho)
__device__ float g_m[NUMIT][Bb*Dd];        // log2_mu stage k
__device__ float g_e[NUMIT][Bb*Nn];        // log2_eta stage k
__device__ float g_Lc[3][Bb*Dd];           // base-2 col-LSE per iteration
__device__ float g_L0row[Bb*Nn];           // base-2 row-LSE of iteration 0

__device__ __forceinline__ float ex2(float v){
    float r; asm("ex2.approx.ftz.f32 %0, %1;" : "=f"(r) : "f"(v)); return r;
}
__device__ __forceinline__ float lg2(float v){
    float r; asm("lg2.approx.ftz.f32 %0, %1;" : "=f"(r) : "f"(v)); return r;
}

__device__ __forceinline__ float warpMax(float v){
#pragma unroll
    for (int o = 16; o > 0; o >>= 1) v = fmaxf(v, __shfl_xor_sync(0xffffffffu, v, o));
    return v;
}
__device__ __forceinline__ float warpSum(float v){
#pragma unroll
    for (int o = 16; o > 0; o >>= 1) v += __shfl_xor_sync(0xffffffffu, v, o);
    return v;
}

// ---------------------------------------------------------------------------
// Precompute log_mu / log_eta trajectories (dual marginals stay separable).
// Internal math in natural log (accurate); stores are scaled to base-2.
// ---------------------------------------------------------------------------
__global__ void __launch_bounds__(512) precomp_kernel(
    const float* __restrict__ p0, const float* __restrict__ q0,
    const float* __restrict__ a2, const float* __restrict__ a3,
    const float* __restrict__ rho)
{
    __shared__ float red[32];
    int b = blockIdx.x, tid = threadIdx.x;
    int wid = tid >> 5, lane = tid & 31;

    float lp = logf(p0[b*Dd + tid]);
    float m = lp, A = 0.f;
    g_m[0][b*Dd + tid] = lp * LOG2E;
    for (int kk = 0; kk < NUMIT-1; kk++){
        float r = rho[kk], a = a2[kk];
        float g = (r*m + a*lp - A) / (r + a);
        float v = warpMax(g);
        if (lane == 0) red[wid] = v;
        __syncthreads();
        if (wid == 0){ float u = (lane < 16) ? red[lane] : -3.4e38f; u = warpMax(u); if (lane==0) red[16]=u; }
        __syncthreads();
        float mx = red[16];
        __syncthreads();
        float s = warpSum(expf(g - mx));
        if (lane == 0) red[wid] = s;
        __syncthreads();
        if (wid == 0){ float u = (lane < 16) ? red[lane] : 0.f; u = warpSum(u); if (lane==0) red[16]=u; }
        __syncthreads();
        float L = mx + logf(red[16]);
        __syncthreads();
        m = g - L;
        A += r * expf(m);
        g_m[kk+1][b*Dd + tid] = m * LOG2E;
    }

    float lq0 = logf(q0[b*Nn + tid] + EPSc);
    float lq1 = logf(q0[b*Nn + tid + 512] + EPSc);
    float e0 = lq0, e1 = lq1, C0 = 0.f, C1 = 0.f;
    g_e[0][b*Nn + tid]       = e0 * LOG2E;
    g_e[0][b*Nn + tid + 512] = e1 * LOG2E;
    for (int kk = 0; kk < NUMIT-1; kk++){
        float r = rho[kk], a = a3[kk];
        float h0 = (r*e0 + a*lq0 - C0) / (r + a);
        float h1 = (r*e1 + a*lq1 - C1) / (r + a);
        float v = warpMax(fmaxf(h0, h1));
        if (lane == 0) red[wid] = v;
        __syncthreads();
        if (wid == 0){ float u = (lane < 16) ? red[lane] : -3.4e38f; u = warpMax(u); if (lane==0) red[16]=u; }
        __syncthreads();
        float mx = red[16];
        __syncthreads();
        float s = warpSum(expf(h0 - mx) + expf(h1 - mx));
        if (lane == 0) red[wid] = s;
        __syncthreads();
        if (wid == 0){ float u = (lane < 16) ? red[lane] : 0.f; u = warpSum(u); if (lane==0) red[16]=u; }
        __syncthreads();
        float L = mx + logf(red[16]);
        __syncthreads();
        e0 = h0 - L; e1 = h1 - L;
        C0 += r * expf(e0); C1 += r * expf(e1);
        g_e[kk+1][b*Nn + tid]       = e0 * LOG2E;
        g_e[kk+1][b*Nn + tid + 512] = e1 * LOG2E;
    }
}

// ---------------------------------------------------------------------------
// Iteration-0 row LSE (base-2), warp-per-row.
//   y2 = x/(rho0*ln2) + log2(q0*p0+eps);  L0row2 = log2-sum-exp2(y2)
// ---------------------------------------------------------------------------
__global__ void __launch_bounds__(256) row0lse_kernel(
    const float* __restrict__ x, const float* __restrict__ p0,
    const float* __restrict__ q0, const float* __restrict__ rho)
{
    int lane = threadIdx.x & 31;
    int row  = blockIdx.x * 8 + (threadIdx.x >> 5);
    int b = row >> 10;
    const float4* x4 = (const float4*)(x + (size_t)row * Dd);
    const float4* p4 = (const float4*)(p0 + (size_t)b * Dd);
    float invr2 = 1.f / (__ldg(rho) * LN2f);
    float q = __ldg(q0 + row);

    float4 y[4];
    float mx = -3.4e38f;
#pragma unroll
    for (int i = 0; i < 4; i++){
        int c = i*32 + lane;
        float4 xv = x4[c], pv = p4[c];
        y[i].x = xv.x*invr2 + lg2(fmaf(q, pv.x, EPSc));
        y[i].y = xv.y*invr2 + lg2(fmaf(q, pv.y, EPSc));
        y[i].z = xv.z*invr2 + lg2(fmaf(q, pv.z, EPSc));
        y[i].w = xv.w*invr2 + lg2(fmaf(q, pv.w, EPSc));
        mx = fmaxf(mx, fmaxf(fmaxf(y[i].x, y[i].y), fmaxf(y[i].z, y[i].w)));
    }
    mx = warpMax(mx);
    float se = 0.f;
#pragma unroll
    for (int i = 0; i < 4; i++)
        se += ex2(y[i].x-mx) + ex2(y[i].y-mx) + ex2(y[i].z-mx) + ex2(y[i].w-mx);
    se = warpSum(se);
    if (lane == 0) g_L0row[row] = mx + lg2(se);
}

// ---------------------------------------------------------------------------
// Col reduce, iteration 0 (base-2): recompute lt2_0 from x.
//   lt2 = m0_2 + x/(r*ln2) + log2(q*p+eps) - L0row2;  v2 = lt2 * (r/(a1+r))
// ---------------------------------------------------------------------------
__global__ void __launch_bounds__(256) colred0_kernel(
    const float* __restrict__ x, const float* __restrict__ p0,
    const float* __restrict__ q0, const float* __restrict__ rho,
    const float* __restrict__ a1)
{
    __shared__ float s_m[256], s_s[256];
    __shared__ float s_q[Nn], s_L[Nn];

    int b = blockIdx.y, tid = threadIdx.x;
    int dc = tid & 31, nr = tid >> 5;
    int d = blockIdx.x * 32 + dc;

    float r      = __ldg(rho);
    float rinv   = r / (__ldg(a1) + r);
    float invr02 = 1.f / (r * LN2f);
    float pd  = p0[b*Dd + d];
    float m0d = g_m[0][b*Dd + d];
    for (int i = tid; i < Nn; i += 256){
        s_q[i] = q0[b*Nn + i];
        s_L[i] = g_L0row[b*Nn + i];
    }
    __syncthreads();

    size_t cb = (size_t)b * Nn * Dd + d;
    float mx = -3.4e38f, sm = 0.f;
    for (int s0 = 0; s0 < Nn/8; s0 += 4){
        float vv[4];
#pragma unroll
        for (int j = 0; j < 4; j++){
            int n = nr + (s0 + j) * 8;
            float xv = x[cb + (size_t)n * Dd];
            float lt2 = m0d + xv*invr02 + lg2(fmaf(s_q[n], pd, EPSc)) - s_L[n];
            vv[j] = lt2 * rinv;
        }
#pragma unroll
        for (int j = 0; j < 4; j++){
            float v = vv[j];
            if (v > mx){ sm = fmaf(sm, ex2(mx - v), 1.f); mx = v; }
            else       { sm += ex2(v - mx); }
        }
    }
    s_m[tid] = mx; s_s[tid] = sm;
    __syncthreads();
    if (tid < 32){
        float M = s_m[tid], S = s_s[tid];
#pragma unroll
        for (int j = 1; j < 8; j++){
            float M2 = s_m[j*32 + tid], S2 = s_s[j*32 + tid];
            float nm = fmaxf(M, M2);
            S = S*ex2(M - nm) + S2*ex2(M2 - nm);
            M = nm;
        }
        g_Lc[0][b*Dd + blockIdx.x*32 + tid] = M + lg2(S);
    }
}

// ---------------------------------------------------------------------------
// Col reduce, k>=1 (base-2): v2 = g_u (already U2 = u/ln2).
// ---------------------------------------------------------------------------
__global__ void __launch_bounds__(256) colredU_kernel(int k)
{
    __shared__ float s_m[256], s_s[256];
    int b = blockIdx.y, tid = threadIdx.x;
    int dc = tid & 31, nr = tid >> 5;
    int d = blockIdx.x * 32 + dc;

    size_t cb = (size_t)b * Nn * Dd + d;
    float mx = -3.4e38f, sm = 0.f;
    for (int s0 = 0; s0 < Nn/8; s0 += 4){
        float vv[4];
#pragma unroll
        for (int j = 0; j < 4; j++){
            int n = nr + (s0 + j) * 8;
            vv[j] = g_u[cb + (size_t)n * Dd];
        }
#pragma unroll
        for (int j = 0; j < 4; j++){
            float v = vv[j];
            if (v > mx){ sm = fmaf(sm, ex2(mx - v), 1.f); mx = v; }
            else       { sm += ex2(v - mx); }
        }
    }
    s_m[tid] = mx; s_s[tid] = sm;
    __syncthreads();
    if (tid < 32){
        float M = s_m[tid], S = s_s[tid];
#pragma unroll
        for (int j = 1; j < 8; j++){
            float M2 = s_m[j*32 + tid], S2 = s_s[j*32 + tid];
            float nm = fmaxf(M, M2);
            S = S*ex2(M - nm) + S2*ex2(M2 - nm);
            M = nm;
        }
        g_Lc[k][b*Dd + blockIdx.x*32 + tid] = M + lg2(S);
    }
}

// ---------------------------------------------------------------------------
// Fused (block-per-row, base-2, single barrier): col-k finalize + row-(k+1).
//   z    = U2*sfac*ln2 - LT2*r*ln2     (value domain)
//   LS2  = e2 - Lc2 + U2
//   zn   = z + r*mk*(2^LT2 - 2^LS2)
//   Y2   = (x - zn)/(rn*ln2) + LS2 ;  L2 = log2-LSE(Y2)
//   LT2' = m2' + Y2 - L2 ;  U2' = zn/(sn*ln2) + (rn/sn)*LT2'
// MODE 0: LT2 recomputed from x (z=0). MODE 2: write 2^LT2' * mask only.
// ---------------------------------------------------------------------------
template<int MODE>
__global__ void __launch_bounds__(128) fused_kernel(
    const float* __restrict__ x, const float* __restrict__ p0,
    const float* __restrict__ q0, const float* __restrict__ mask,
    const float* __restrict__ rho, const float* __restrict__ a1,
    float* __restrict__ lt_buf, int k)
{
    __shared__ float sm_m[4], sm_s[4];
    int row = blockIdx.x, b = row >> 10;
    int tid = threadIdx.x, wid = tid >> 5, lane = tid & 31;
    size_t base = (size_t)row * Dd;

    float r     = __ldg(rho + k);
    float sfac  = __ldg(a1 + k) + r;
    float rn    = __ldg(rho + k + 1);
    float mk    = __ldg(mask + row);
    float e2    = g_e[k][row];
    float rm    = r * mk;
    float invrn2 = 1.f / (rn * LN2f);
    float sfacl  = sfac * LN2f;
    float rl     = r * LN2f;
    float sn     = __ldg(a1 + k + 1) + rn;
    float c1     = (MODE == 2) ? 0.f : 1.f / (sn * LN2f);
    float c2     = (MODE == 2) ? 0.f : rn / sn;

    float4 xv = ((const float4*)(x + base))[tid];
    float4 Lc = ((const float4*)(g_Lc[k] + (size_t)b*Dd))[tid];

    float4 lt, uv;
    if (MODE == 0){
        float q      = __ldg(q0 + row);
        float L0r    = g_L0row[row];
        float invr02 = 1.f / (r * LN2f);
        float rinv   = r / sfac;
        float4 pv = ((const float4*)(p0 + (size_t)b*Dd))[tid];
        float4 m0 = ((const float4*)(g_m[0] + (size_t)b*Dd))[tid];
        lt.x = m0.x + xv.x*invr02 + lg2(fmaf(q, pv.x, EPSc)) - L0r;
        lt.y = m0.y + xv.y*invr02 + lg2(fmaf(q, pv.y, EPSc)) - L0r;
        lt.z = m0.z + xv.z*invr02 + lg2(fmaf(q, pv.z, EPSc)) - L0r;
        lt.w = m0.w + xv.w*invr02 + lg2(fmaf(q, pv.w, EPSc)) - L0r;
        uv.x = lt.x*rinv; uv.y = lt.y*rinv;
        uv.z = lt.z*rinv; uv.w = lt.w*rinv;
    } else {
        lt = ((const float4*)(lt_buf + base))[tid];
        uv = ((const float4*)(g_u + base))[tid];
    }

    float4 y, zn;
    {
        float z, ls;
        z = (MODE == 0) ? 0.f : uv.x*sfacl - lt.x*rl;
        ls = e2 - Lc.x + uv.x;
        zn.x = fmaf(rm, ex2(lt.x) - ex2(ls), z);
        y.x  = fmaf(xv.x - zn.x, invrn2, ls);
        z = (MODE == 0) ? 0.f : uv.y*sfacl - lt.y*rl;
        ls = e2 - Lc.y + uv.y;
        zn.y = fmaf(rm, ex2(lt.y) - ex2(ls), z);
        y.y  = fmaf(xv.y - zn.y, invrn2, ls);
        z = (MODE == 0) ? 0.f : uv.z*sfacl - lt.z*rl;
        ls = e2 - Lc.z + uv.z;
        zn.z = fmaf(rm, ex2(lt.z) - ex2(ls), z);
        y.z  = fmaf(xv.z - zn.z, invrn2, ls);
        z = (MODE == 0) ? 0.f : uv.w*sfacl - lt.w*rl;
        ls = e2 - Lc.w + uv.w;
        zn.w = fmaf(rm, ex2(lt.w) - ex2(ls), z);
        y.w  = fmaf(xv.w - zn.w, invrn2, ls);
    }

    // one-barrier block LSE: per-warp (max, sum) then 4-pair combine
    float mx = fmaxf(fmaxf(y.x, y.y), fmaxf(y.z, y.w));
    mx = warpMax(mx);
    float se = ex2(y.x-mx) + ex2(y.y-mx) + ex2(y.z-mx) + ex2(y.w-mx);
    se = warpSum(se);
    if (lane == 0){ sm_m[wid] = mx; sm_s[wid] = se; }
    __syncthreads();
    float M0 = sm_m[0], M1 = sm_m[1], M2v = sm_m[2], M3 = sm_m[3];
    float Mf = fmaxf(fmaxf(M0, M1), fmaxf(M2v, M3));
    float Sf = sm_s[0]*ex2(M0-Mf) + sm_s[1]*ex2(M1-Mf)
             + sm_s[2]*ex2(M2v-Mf) + sm_s[3]*ex2(M3-Mf);
    float L2 = Mf + lg2(Sf);

    float4 mn = ((const float4*)(g_m[k+1] + (size_t)b*Dd))[tid];
    float4 o;
    o.x = mn.x + y.x - L2;
    o.y = mn.y + y.y - L2;
    o.z = mn.z + y.z - L2;
    o.w = mn.w + y.w - L2;
    if (MODE == 2){
        o.x = ex2(o.x)*mk; o.y = ex2(o.y)*mk;
        o.z = ex2(o.z)*mk; o.w = ex2(o.w)*mk;
    } else {
        float4 un;
        un.x = fmaf(o.x, c2, zn.x*c1);
        un.y = fmaf(o.y, c2, zn.y*c1);
        un.z = fmaf(o.z, c2, zn.z*c1);
        un.w = fmaf(o.w, c2, zn.w*c1);
        ((float4*)(g_u + base))[tid] = un;
    }
    ((float4*)(lt_buf + base))[tid] = o;
}

// ---------------------------------------------------------------------------
extern "C" void kernel_launch(void* const* d_in, const int* in_sizes, int n_in,
                              void* d_out, int out_size)
{
    const float* x    = (const float*)d_in[0];
    const float* p0   = (const float*)d_in[1];
    const float* q0   = (const float*)d_in[2];
    const float* a1   = (const float*)d_in[3];
    const float* a2   = (const float*)d_in[4];
    const float* a3   = (const float*)d_in[5];
    const float* rho  = (const float*)d_in[6];
    const float* mask = (const float*)d_in[7];
    float* out = (float*)d_out;   // doubles as the lt2 buffer between passes

    precomp_kernel<<<Bb, 512>>>(p0, q0, a2, a3, rho);

    dim3 cgrid(Dd / 32, Bb);
    row0lse_kernel<<<Bb*Nn/8, 256>>>(x, p0, q0, rho);

    colred0_kernel<<<cgrid, 256>>>(x, p0, q0, rho, a1);
    fused_kernel<0><<<Bb*Nn, 128>>>(x, p0, q0, mask, rho, a1, out, 0);

    colredU_kernel<<<cgrid, 256>>>(1);
    fused_kernel<1><<<Bb*Nn, 128>>>(x, p0, q0, mask, rho, a1, out, 1);

    colredU_kernel<<<cgrid, 256>>>(2);
    fused_kernel<2><<<Bb*Nn, 128>>>(x, p0, q0, mask, rho, a1, out, 2);
}

// round 7
// speedup vs baseline: 2.0343x; 1.0187x over previous
#include <cuda_runtime.h>
#include <math.h>

#define Bb 64
#define Nn 1024
#define Dd 512
#define TOT (Bb*Nn*Dd)
#define NUMIT 4
#define EPSc 1e-8f
#define LOG2E 1.44269504088896340736f
#define LN2f  0.69314718055994530942f

// Scratch (device globals). All log-domain state in BASE 2.
// Per-element state is ONLY z (B,N,D). The dual u is a closed form:
//   U_k = alpha_k*x + beta_k*g + A_k[b,d] + B_k[b,n],  g = lg2(q0*p0+eps)
__device__ float g_z[TOT];
__device__ float g_m[NUMIT][Bb*Dd];        // log2_mu stage k
__device__ float g_e[NUMIT][Bb*Nn];        // log2_eta stage k
__device__ float g_A[3][Bb*Dd];            // U-decomposition (b,d) table
__device__ float g_B[3][Bb*Nn];            // U-decomposition (b,n) table
__device__ float g_Lc[3][Bb*Dd];           // base-2 col-LSE of U_k
__device__ float g_Lrow[3][Bb*Nn];         // base-2 row-LSE stage k

__device__ __forceinline__ float ex2(float v){
    float r; asm("ex2.approx.ftz.f32 %0, %1;" : "=f"(r) : "f"(v)); return r;
}
__device__ __forceinline__ float lg2(float v){
    float r; asm("lg2.approx.ftz.f32 %0, %1;" : "=f"(r) : "f"(v)); return r;
}
__device__ __forceinline__ float warpMax(float v){
#pragma unroll
    for (int o = 16; o > 0; o >>= 1) v = fmaxf(v, __shfl_xor_sync(0xffffffffu, v, o));
    return v;
}
__device__ __forceinline__ float warpSum(float v){
#pragma unroll
    for (int o = 16; o > 0; o >>= 1) v += __shfl_xor_sync(0xffffffffu, v, o);
    return v;
}

// alpha/beta recursion: U_k = alpha_k*x + beta_k*g + tables
__device__ __forceinline__ void alphabeta(const float* rho, const float* a1,
                                          int k, float& al, float& be){
    float s = a1[0] + rho[0];
    al = 1.f/(s*LN2f); be = rho[0]/s;
    for (int j = 1; j <= k; j++){
        s = a1[j] + rho[j];
        al = (1.f/LN2f + rho[j]*al)/s;
        be = rho[j]*be/s;
    }
}

// ---------------------------------------------------------------------------
// Precompute log2_mu / log2_eta trajectories (dual marginals separable).
// ---------------------------------------------------------------------------
__global__ void __launch_bounds__(512) precomp_kernel(
    const float* __restrict__ p0, const float* __restrict__ q0,
    const float* __restrict__ a2, const float* __restrict__ a3,
    const float* __restrict__ rho)
{
    __shared__ float red[32];
    int b = blockIdx.x, tid = threadIdx.x;
    int wid = tid >> 5, lane = tid & 31;

    float lp = logf(p0[b*Dd + tid]);
    float m = lp, A = 0.f;
    g_m[0][b*Dd + tid] = lp * LOG2E;
    for (int kk = 0; kk < NUMIT-1; kk++){
        float r = rho[kk], a = a2[kk];
        float g = (r*m + a*lp - A) / (r + a);
        float v = warpMax(g);
        if (lane == 0) red[wid] = v;
        __syncthreads();
        if (wid == 0){ float u = (lane < 16) ? red[lane] : -3.4e38f; u = warpMax(u); if (lane==0) red[16]=u; }
        __syncthreads();
        float mx = red[16];
        __syncthreads();
        float s = warpSum(expf(g - mx));
        if (lane == 0) red[wid] = s;
        __syncthreads();
        if (wid == 0){ float u = (lane < 16) ? red[lane] : 0.f; u = warpSum(u); if (lane==0) red[16]=u; }
        __syncthreads();
        float L = mx + logf(red[16]);
        __syncthreads();
        m = g - L;
        A += r * expf(m);
        g_m[kk+1][b*Dd + tid] = m * LOG2E;
    }

    float lq0 = logf(q0[b*Nn + tid] + EPSc);
    float lq1 = logf(q0[b*Nn + tid + 512] + EPSc);
    float e0 = lq0, e1 = lq1, C0 = 0.f, C1 = 0.f;
    g_e[0][b*Nn + tid]       = e0 * LOG2E;
    g_e[0][b*Nn + tid + 512] = e1 * LOG2E;
    for (int kk = 0; kk < NUMIT-1; kk++){
        float r = rho[kk], a = a3[kk];
        float h0 = (r*e0 + a*lq0 - C0) / (r + a);
        float h1 = (r*e1 + a*lq1 - C1) / (r + a);
        float v = warpMax(fmaxf(h0, h1));
        if (lane == 0) red[wid] = v;
        __syncthreads();
        if (wid == 0){ float u = (lane < 16) ? red[lane] : -3.4e38f; u = warpMax(u); if (lane==0) red[16]=u; }
        __syncthreads();
        float mx = red[16];
        __syncthreads();
        float s = warpSum(expf(h0 - mx) + expf(h1 - mx));
        if (lane == 0) red[wid] = s;
        __syncthreads();
        if (wid == 0){ float u = (lane < 16) ? red[lane] : 0.f; u = warpSum(u); if (lane==0) red[16]=u; }
        __syncthreads();
        float L = mx + logf(red[16]);
        __syncthreads();
        e0 = h0 - L; e1 = h1 - L;
        C0 += r * expf(e0); C1 += r * expf(e1);
        g_e[kk+1][b*Nn + tid]       = e0 * LOG2E;
        g_e[kk+1][b*Nn + tid + 512] = e1 * LOG2E;
    }
}

// ---------------------------------------------------------------------------
// Iteration-0 row LSE (base-2), warp-per-row: Lrow_0 = lse2_d(x/(r0 ln2) + g)
// ---------------------------------------------------------------------------
__global__ void __launch_bounds__(256) row0lse_kernel(
    const float* __restrict__ x, const float* __restrict__ p0,
    const float* __restrict__ q0, const float* __restrict__ rho)
{
    int lane = threadIdx.x & 31;
    int row  = blockIdx.x * 8 + (threadIdx.x >> 5);
    int b = row >> 10;
    const float4* x4 = (const float4*)(x + (size_t)row * Dd);
    const float4* p4 = (const float4*)(p0 + (size_t)b * Dd);
    float invr2 = 1.f / (__ldg(rho) * LN2f);
    float q = __ldg(q0 + row);

    float4 y[4];
    float mx = -3.4e38f;
#pragma unroll
    for (int i = 0; i < 4; i++){
        int c = i*32 + lane;
        float4 xv = x4[c], pv = p4[c];
        y[i].x = xv.x*invr2 + lg2(fmaf(q, pv.x, EPSc));
        y[i].y = xv.y*invr2 + lg2(fmaf(q, pv.y, EPSc));
        y[i].z = xv.z*invr2 + lg2(fmaf(q, pv.z, EPSc));
        y[i].w = xv.w*invr2 + lg2(fmaf(q, pv.w, EPSc));
        mx = fmaxf(mx, fmaxf(fmaxf(y[i].x, y[i].y), fmaxf(y[i].z, y[i].w)));
    }
    mx = warpMax(mx);
    float se = 0.f;
#pragma unroll
    for (int i = 0; i < 4; i++)
        se += ex2(y[i].x-mx) + ex2(y[i].y-mx) + ex2(y[i].z-mx) + ex2(y[i].w-mx);
    se = warpSum(se);
    if (lane == 0) g_Lrow[0][row] = mx + lg2(se);
}

// ---------------------------------------------------------------------------
// Table maintenance (tiny): A_k, B_k from recursion.
//   k=0: A0 = f*m2_0,                B0 = -f*Lrow_0
//   k>0: Ak = f*(A_{k-1} - Lc_{k-1} + m2_k),  Bk = f*(B_{k-1} + e2_{k-1} - Lrow_k)
// with f = rho_k/(a1_k+rho_k). One block per batch, 512 threads.
// ---------------------------------------------------------------------------
__global__ void __launch_bounds__(512) tables_kernel(
    const float* __restrict__ rho, const float* __restrict__ a1, int k)
{
    int b = blockIdx.x, tid = threadIdx.x;
    float rk = rho[k];
    float f = rk / (a1[k] + rk);
    int id = b*Dd + tid;
    if (k == 0){
        g_A[0][id] = f * g_m[0][id];
        int in0 = b*Nn + tid, in1 = in0 + 512;
        g_B[0][in0] = -f * g_Lrow[0][in0];
        g_B[0][in1] = -f * g_Lrow[0][in1];
    } else {
        g_A[k][id] = f * (g_A[k-1][id] - g_Lc[k-1][id] + g_m[k][id]);
        int in0 = b*Nn + tid, in1 = in0 + 512;
        g_B[k][in0] = f * (g_B[k-1][in0] + g_e[k-1][in0] - g_Lrow[k][in0]);
        g_B[k][in1] = f * (g_B[k-1][in1] + g_e[k-1][in1] - g_Lrow[k][in1]);
    }
}

// ---------------------------------------------------------------------------
// Col reduce (reads ONLY x): Lc_k = lse2_n(U_k),
//   U_k = alpha_k*x + beta_k*g + A_k[b,d] + B_k[b,n]
// Block = (b, 32 d-cols), 256 threads.
// ---------------------------------------------------------------------------
__global__ void __launch_bounds__(256) colred_kernel(
    const float* __restrict__ x, const float* __restrict__ p0,
    const float* __restrict__ q0, const float* __restrict__ rho,
    const float* __restrict__ a1, int k)
{
    __shared__ float s_m[256], s_s[256];
    __shared__ float s_q[Nn], s_B[Nn];

    int b = blockIdx.y, tid = threadIdx.x;
    int dc = tid & 31, nr = tid >> 5;
    int d = blockIdx.x * 32 + dc;

    float al, be;
    alphabeta(rho, a1, k, al, be);

    float pd = p0[b*Dd + d];
    float Ad = g_A[k][b*Dd + d];
    for (int i = tid; i < Nn; i += 256){
        s_q[i] = q0[b*Nn + i];
        s_B[i] = g_B[k][b*Nn + i];
    }
    __syncthreads();

    size_t cb = (size_t)b * Nn * Dd + d;
    float mx = -3.4e38f, sm = 0.f;
    for (int s0 = 0; s0 < Nn/8; s0 += 4){
        float vv[4];
#pragma unroll
        for (int j = 0; j < 4; j++){
            int n = nr + (s0 + j) * 8;
            float xv = x[cb + (size_t)n * Dd];
            float g = lg2(fmaf(s_q[n], pd, EPSc));
            vv[j] = fmaf(al, xv, fmaf(be, g, Ad + s_B[n]));
        }
#pragma unroll
        for (int j = 0; j < 4; j++){
            float v = vv[j];
            if (v > mx){ sm = fmaf(sm, ex2(mx - v), 1.f); mx = v; }
            else       { sm += ex2(v - mx); }
        }
    }
    s_m[tid] = mx; s_s[tid] = sm;
    __syncthreads();
    if (tid < 32){
        float M = s_m[tid], S = s_s[tid];
#pragma unroll
        for (int j = 1; j < 8; j++){
            float M2 = s_m[j*32 + tid], S2 = s_s[j*32 + tid];
            float nm = fmaxf(M, M2);
            S = S*ex2(M - nm) + S2*ex2(M2 - nm);
            M = nm;
        }
        g_Lc[k][b*Dd + blockIdx.x*32 + tid] = M + lg2(S);
    }
}

// ---------------------------------------------------------------------------
// Fused iteration kernel (block-per-row). MODE = k in {0,1,2}.
//   MODE 0: z=0; lt0 = m2_0 + x/(r0 ln2) + g - Lrow_0
//   MODE>=1: lt_k = (x - z_k)/(r_k ln2) + a_{k-1} x + b_{k-1} g + (s_k/r_k)(A_k + B_k)
//   U_k = (z_k/ln2 + r_k lt_k)/s_k ;  ls_k = e2_k - Lc_k + U_k
//   z' = z + r_k mk (2^lt - 2^ls)
//   Y = (x - z')/(r_{k+1} ln2) + ls_k ;  Lrow_{k+1} = lse2_d(Y)
//   MODE<=1: write z', Lrow_{k+1}.  MODE 2: out = 2^(m2_3 + Y - Lrow_3)*mk.
// ---------------------------------------------------------------------------
template<int MODE>
__global__ void __launch_bounds__(128) fused_kernel(
    const float* __restrict__ x, const float* __restrict__ p0,
    const float* __restrict__ q0, const float* __restrict__ mask,
    const float* __restrict__ rho, const float* __restrict__ a1,
    float* __restrict__ out)
{
    __shared__ float sm_m[4], sm_s[4];
    const int k = MODE;
    int row = blockIdx.x, b = row >> 10;
    int tid = threadIdx.x, wid = tid >> 5, lane = tid & 31;
    size_t base = (size_t)row * Dd;

    float rk = __ldg(rho + k);
    float sk = __ldg(a1 + k) + rk;
    float rn = __ldg(rho + k + 1);      // rho[3] valid for MODE 2
    float mk = __ldg(mask + row);
    float e2 = g_e[k][row];
    float q  = __ldg(q0 + row);
    float invrk2 = 1.f / (rk * LN2f);
    float invrn2 = 1.f / (rn * LN2f);
    float rkm = rk * mk;
    float invsk = 1.f / sk;
    float rkdsk = rk * invsk;
    float il2sk = 1.f / (LN2f * sk);

    float Brow = 0.f, al = 0.f, be = 0.f, skdrk = 0.f, Lr0 = 0.f;
    if (MODE == 0){
        Lr0 = g_Lrow[0][row];
    } else {
        Brow = g_B[k][row];
        alphabeta(rho, a1, k-1, al, be);
        skdrk = sk / rk;
    }

    float4 xv = ((const float4*)(x + base))[tid];
    float4 pv = ((const float4*)(p0 + (size_t)b*Dd))[tid];
    float4 Lc = ((const float4*)(g_Lc[k] + (size_t)b*Dd))[tid];
    float4 zv = make_float4(0.f,0.f,0.f,0.f);
    if (MODE != 0) zv = ((const float4*)(g_z + base))[tid];

    float4 gv;
    gv.x = lg2(fmaf(q, pv.x, EPSc));
    gv.y = lg2(fmaf(q, pv.y, EPSc));
    gv.z = lg2(fmaf(q, pv.z, EPSc));
    gv.w = lg2(fmaf(q, pv.w, EPSc));

    float4 lt;
    if (MODE == 0){
        float4 m0 = ((const float4*)(g_m[0] + (size_t)b*Dd))[tid];
        lt.x = m0.x + xv.x*invrk2 + gv.x - Lr0;
        lt.y = m0.y + xv.y*invrk2 + gv.y - Lr0;
        lt.z = m0.z + xv.z*invrk2 + gv.z - Lr0;
        lt.w = m0.w + xv.w*invrk2 + gv.w - Lr0;
    } else {
        float4 Av = ((const float4*)(g_A[k] + (size_t)b*Dd))[tid];
        lt.x = (xv.x - zv.x)*invrk2 + fmaf(al, xv.x, fmaf(be, gv.x, skdrk*(Av.x + Brow)));
        lt.y = (xv.y - zv.y)*invrk2 + fmaf(al, xv.y, fmaf(be, gv.y, skdrk*(Av.y + Brow)));
        lt.z = (xv.z - zv.z)*invrk2 + fmaf(al, xv.z, fmaf(be, gv.z, skdrk*(Av.z + Brow)));
        lt.w = (xv.w - zv.w)*invrk2 + fmaf(al, xv.w, fmaf(be, gv.w, skdrk*(Av.w + Brow)));
    }

    float4 y, zn;
    {
        float U, ls;
        U = zv.x*il2sk + lt.x*rkdsk;  ls = e2 - Lc.x + U;
        zn.x = fmaf(rkm, ex2(lt.x) - ex2(ls), zv.x);
        y.x  = fmaf(xv.x - zn.x, invrn2, ls);
        U = zv.y*il2sk + lt.y*rkdsk;  ls = e2 - Lc.y + U;
        zn.y = fmaf(rkm, ex2(lt.y) - ex2(ls), zv.y);
        y.y  = fmaf(xv.y - zn.y, invrn2, ls);
        U = zv.z*il2sk + lt.z*rkdsk;  ls = e2 - Lc.z + U;
        zn.z = fmaf(rkm, ex2(lt.z) - ex2(ls), zv.z);
        y.z  = fmaf(xv.z - zn.z, invrn2, ls);
        U = zv.w*il2sk + lt.w*rkdsk;  ls = e2 - Lc.w + U;
        zn.w = fmaf(rkm, ex2(lt.w) - ex2(ls), zv.w);
        y.w  = fmaf(xv.w - zn.w, invrn2, ls);
    }

    // one-barrier block LSE over y (512 values)
    float mx = fmaxf(fmaxf(y.x, y.y), fmaxf(y.z, y.w));
    mx = warpMax(mx);
    float se = ex2(y.x-mx) + ex2(y.y-mx) + ex2(y.z-mx) + ex2(y.w-mx);
    se = warpSum(se);
    if (lane == 0){ sm_m[wid] = mx; sm_s[wid] = se; }
    __syncthreads();
    float M0 = sm_m[0], M1 = sm_m[1], M2v = sm_m[2], M3 = sm_m[3];
    float Mf = fmaxf(fmaxf(M0, M1), fmaxf(M2v, M3));
    float Sf = sm_s[0]*ex2(M0-Mf) + sm_s[1]*ex2(M1-Mf)
             + sm_s[2]*ex2(M2v-Mf) + sm_s[3]*ex2(M3-Mf);
    float L2 = Mf + lg2(Sf);

    if (MODE == 2){
        float4 m3 = ((const float4*)(g_m[3] + (size_t)b*Dd))[tid];
        float4 o;
        o.x = ex2(m3.x + y.x - L2)*mk;
        o.y = ex2(m3.y + y.y - L2)*mk;
        o.z = ex2(m3.z + y.z - L2)*mk;
        o.w = ex2(m3.w + y.w - L2)*mk;
        ((float4*)(out + base))[tid] = o;
    } else {
        ((float4*)(g_z + base))[tid] = zn;
        if (tid == 0) g_Lrow[k+1][row] = L2;
    }
}

// ---------------------------------------------------------------------------
extern "C" void kernel_launch(void* const* d_in, const int* in_sizes, int n_in,
                              void* d_out, int out_size)
{
    const float* x    = (const float*)d_in[0];
    const float* p0   = (const float*)d_in[1];
    const float* q0   = (const float*)d_in[2];
    const float* a1   = (const float*)d_in[3];
    const float* a2   = (const float*)d_in[4];
    const float* a3   = (const float*)d_in[5];
    const float* rho  = (const float*)d_in[6];
    const float* mask = (const float*)d_in[7];
    float* out = (float*)d_out;

    precomp_kernel<<<Bb, 512>>>(p0, q0, a2, a3, rho);
    row0lse_kernel<<<Bb*Nn/8, 256>>>(x, p0, q0, rho);

    dim3 cgrid(Dd / 32, Bb);

    tables_kernel<<<Bb, 512>>>(rho, a1, 0);
    colred_kernel<<<cgrid, 256>>>(x, p0, q0, rho, a1, 0);
    fused_kernel<0><<<Bb*Nn, 128>>>(x, p0, q0, mask, rho, a1, out);

    tables_kernel<<<Bb, 512>>>(rho, a1, 1);
    colred_kernel<<<cgrid, 256>>>(x, p0, q0, rho, a1, 1);
    fused_kernel<1><<<Bb*Nn, 128>>>(x, p0, q0, mask, rho, a1, out);

    tables_kernel<<<Bb, 512>>>(rho, a1, 2);
    colred_kernel<<<cgrid, 256>>>(x, p0, q0, rho, a1, 2);
    fused_kernel<2><<<Bb*Nn, 128>>>(x, p0, q0, mask, rho, a1, out);
}

// round 8
// speedup vs baseline: 2.2718x; 1.1168x over previous
#include <cuda_runtime.h>
#include <math.h>

#define Bb 64
#define Nn 1024
#define Dd 512
#define TOT (Bb*Nn*Dd)
#define NUMIT 4
#define EPSc 1e-8f
#define LOG2E 1.44269504088896340736f
#define LN2f  0.69314718055994530942f

// Scratch (device globals). All log-domain state in BASE 2.
// Per-element state is ONLY z (B,N,D). The dual u is a closed form:
//   U_k = alpha_k*x + beta_k*g + A_k[b,d] + B_k[b,n],  g = lg2(q0*p0+eps)
__device__ float g_z[TOT];
__device__ float g_m[NUMIT][Bb*Dd];        // log2_mu stage k
__device__ float g_e[NUMIT][Bb*Nn];        // log2_eta stage k
__device__ float g_A[3][Bb*Dd];            // U-decomposition (b,d) table
__device__ float g_B[3][Bb*Nn];            // U-decomposition (b,n) table
__device__ float g_Lc[3][Bb*Dd];           // base-2 col-LSE of U_k
__device__ float g_Lrow[3][Bb*Nn];         // base-2 row-LSE stage k
__device__ float g_sc[3][10];              // per-iteration scalar constants
__device__ float g_invr0l2;                // 1/(rho0*ln2)

// g_sc layout: 0:1/(rk ln2)  1:1/(ln2 sk)  2:rk/sk  3:1/(rn ln2)  4:rk
//              5:sk/rk       6:al_k        7:be_k   8:al_{k-1}    9:be_{k-1}

__device__ __forceinline__ float ex2(float v){
    float r; asm("ex2.approx.ftz.f32 %0, %1;" : "=f"(r) : "f"(v)); return r;
}
__device__ __forceinline__ float lg2(float v){
    float r; asm("lg2.approx.ftz.f32 %0, %1;" : "=f"(r) : "f"(v)); return r;
}
__device__ __forceinline__ float warpMax(float v){
#pragma unroll
    for (int o = 16; o > 0; o >>= 1) v = fmaxf(v, __shfl_xor_sync(0xffffffffu, v, o));
    return v;
}
__device__ __forceinline__ float warpSum(float v){
#pragma unroll
    for (int o = 16; o > 0; o >>= 1) v += __shfl_xor_sync(0xffffffffu, v, o);
    return v;
}

// ---------------------------------------------------------------------------
// Precompute log2_mu / log2_eta trajectories (dual marginals separable).
// ---------------------------------------------------------------------------
__global__ void __launch_bounds__(512) precomp_kernel(
    const float* __restrict__ p0, const float* __restrict__ q0,
    const float* __restrict__ a2, const float* __restrict__ a3,
    const float* __restrict__ rho)
{
    __shared__ float red[32];
    int b = blockIdx.x, tid = threadIdx.x;
    int wid = tid >> 5, lane = tid & 31;

    if (b == 0 && tid == 0) g_invr0l2 = 1.f / (rho[0] * LN2f);

    float lp = logf(p0[b*Dd + tid]);
    float m = lp, A = 0.f;
    g_m[0][b*Dd + tid] = lp * LOG2E;
    for (int kk = 0; kk < NUMIT-1; kk++){
        float r = rho[kk], a = a2[kk];
        float g = (r*m + a*lp - A) / (r + a);
        float v = warpMax(g);
        if (lane == 0) red[wid] = v;
        __syncthreads();
        if (wid == 0){ float u = (lane < 16) ? red[lane] : -3.4e38f; u = warpMax(u); if (lane==0) red[16]=u; }
        __syncthreads();
        float mx = red[16];
        __syncthreads();
        float s = warpSum(expf(g - mx));
        if (lane == 0) red[wid] = s;
        __syncthreads();
        if (wid == 0){ float u = (lane < 16) ? red[lane] : 0.f; u = warpSum(u); if (lane==0) red[16]=u; }
        __syncthreads();
        float L = mx + logf(red[16]);
        __syncthreads();
        m = g - L;
        A += r * expf(m);
        g_m[kk+1][b*Dd + tid] = m * LOG2E;
    }

    float lq0 = logf(q0[b*Nn + tid] + EPSc);
    float lq1 = logf(q0[b*Nn + tid + 512] + EPSc);
    float e0 = lq0, e1 = lq1, C0 = 0.f, C1 = 0.f;
    g_e[0][b*Nn + tid]       = e0 * LOG2E;
    g_e[0][b*Nn + tid + 512] = e1 * LOG2E;
    for (int kk = 0; kk < NUMIT-1; kk++){
        float r = rho[kk], a = a3[kk];
        float h0 = (r*e0 + a*lq0 - C0) / (r + a);
        float h1 = (r*e1 + a*lq1 - C1) / (r + a);
        float v = warpMax(fmaxf(h0, h1));
        if (lane == 0) red[wid] = v;
        __syncthreads();
        if (wid == 0){ float u = (lane < 16) ? red[lane] : -3.4e38f; u = warpMax(u); if (lane==0) red[16]=u; }
        __syncthreads();
        float mx = red[16];
        __syncthreads();
        float s = warpSum(expf(h0 - mx) + expf(h1 - mx));
        if (lane == 0) red[wid] = s;
        __syncthreads();
        if (wid == 0){ float u = (lane < 16) ? red[lane] : 0.f; u = warpSum(u); if (lane==0) red[16]=u; }
        __syncthreads();
        float L = mx + logf(red[16]);
        __syncthreads();
        e0 = h0 - L; e1 = h1 - L;
        C0 += r * expf(e0); C1 += r * expf(e1);
        g_e[kk+1][b*Nn + tid]       = e0 * LOG2E;
        g_e[kk+1][b*Nn + tid + 512] = e1 * LOG2E;
    }
}

// ---------------------------------------------------------------------------
// Iteration-0 row LSE (base-2), warp-per-row: Lrow_0 = lse2_d(x/(r0 ln2) + g)
// ---------------------------------------------------------------------------
__global__ void __launch_bounds__(256) row0lse_kernel(
    const float* __restrict__ x, const float* __restrict__ p0,
    const float* __restrict__ q0)
{
    int lane = threadIdx.x & 31;
    int row  = blockIdx.x * 8 + (threadIdx.x >> 5);
    int b = row >> 10;
    const float4* x4 = (const float4*)(x + (size_t)row * Dd);
    const float4* p4 = (const float4*)(p0 + (size_t)b * Dd);
    float invr2 = g_invr0l2;
    float q = __ldg(q0 + row);

    float4 y[4];
    float mx = -3.4e38f;
#pragma unroll
    for (int i = 0; i < 4; i++){
        int c = i*32 + lane;
        float4 xv = x4[c], pv = p4[c];
        y[i].x = fmaf(xv.x, invr2, lg2(fmaf(q, pv.x, EPSc)));
        y[i].y = fmaf(xv.y, invr2, lg2(fmaf(q, pv.y, EPSc)));
        y[i].z = fmaf(xv.z, invr2, lg2(fmaf(q, pv.z, EPSc)));
        y[i].w = fmaf(xv.w, invr2, lg2(fmaf(q, pv.w, EPSc)));
        mx = fmaxf(mx, fmaxf(fmaxf(y[i].x, y[i].y), fmaxf(y[i].z, y[i].w)));
    }
    mx = warpMax(mx);
    float se = 0.f;
#pragma unroll
    for (int i = 0; i < 4; i++)
        se += ex2(y[i].x-mx) + ex2(y[i].y-mx) + ex2(y[i].z-mx) + ex2(y[i].w-mx);
    se = warpSum(se);
    if (lane == 0) g_Lrow[0][row] = mx + lg2(se);
}

// ---------------------------------------------------------------------------
// Table + scalar maintenance (tiny).
//   k=0: A0 = f*m2_0,  B0 = -f*Lrow_0
//   k>0: Ak = f*(A_{k-1} - Lc_{k-1} + m2_k),  Bk = f*(B_{k-1} + e2_{k-1} - Lrow_k)
// Plus all hot-kernel scalar constants for iteration k (block 0, thread 0).
// ---------------------------------------------------------------------------
__global__ void __launch_bounds__(512) tables_kernel(
    const float* __restrict__ rho, const float* __restrict__ a1, int k)
{
    int b = blockIdx.x, tid = threadIdx.x;
    float rk = rho[k];
    float f = rk / (a1[k] + rk);

    if (b == 0 && tid == 0){
        float sk = a1[k] + rk;
        float rn = rho[k+1];
        g_sc[k][0] = 1.f / (rk * LN2f);
        g_sc[k][1] = 1.f / (LN2f * sk);
        g_sc[k][2] = rk / sk;
        g_sc[k][3] = 1.f / (rn * LN2f);
        g_sc[k][4] = rk;
        g_sc[k][5] = sk / rk;
        float s0 = a1[0] + rho[0];
        float al = 1.f/(s0*LN2f), be = rho[0]/s0;
        float alp = 0.f, bep = 0.f;
        for (int j = 1; j <= k; j++){
            alp = al; bep = be;
            float s = a1[j] + rho[j];
            al = (1.f/LN2f + rho[j]*al)/s;
            be = rho[j]*be/s;
        }
        g_sc[k][6] = al;  g_sc[k][7] = be;
        g_sc[k][8] = alp; g_sc[k][9] = bep;
    }

    int id = b*Dd + tid;
    if (k == 0){
        g_A[0][id] = f * g_m[0][id];
        int in0 = b*Nn + tid, in1 = in0 + 512;
        g_B[0][in0] = -f * g_Lrow[0][in0];
        g_B[0][in1] = -f * g_Lrow[0][in1];
    } else {
        g_A[k][id] = f * (g_A[k-1][id] - g_Lc[k-1][id] + g_m[k][id]);
        int in0 = b*Nn + tid, in1 = in0 + 512;
        g_B[k][in0] = f * (g_B[k-1][in0] + g_e[k-1][in0] - g_Lrow[k][in0]);
        g_B[k][in1] = f * (g_B[k-1][in1] + g_e[k-1][in1] - g_Lrow[k][in1]);
    }
}

// ---------------------------------------------------------------------------
// Col reduce (reads ONLY x): Lc_k = lse2_n(U_k),
//   U_k = al*x + be*g + A_k[b,d] + B_k[b,n]
// 4 independent branchless online-LSE chains per thread (no loop-carried
// dependency across the batched loads); merged at the end.
// ---------------------------------------------------------------------------
__global__ void __launch_bounds__(256) colred_kernel(
    const float* __restrict__ x, const float* __restrict__ p0,
    const float* __restrict__ q0, int k)
{
    __shared__ float s_m[256], s_s[256];
    __shared__ float s_q[Nn], s_B[Nn];

    int b = blockIdx.y, tid = threadIdx.x;
    int dc = tid & 31, nr = tid >> 5;
    int d = blockIdx.x * 32 + dc;

    float al = g_sc[k][6], be = g_sc[k][7];
    float pd = p0[b*Dd + d];
    float Ad = g_A[k][b*Dd + d];
    for (int i = tid; i < Nn; i += 256){
        s_q[i] = q0[b*Nn + i];
        s_B[i] = g_B[k][b*Nn + i];
    }
    __syncthreads();

    size_t cb = (size_t)b * Nn * Dd + d;
    float m0 = -3.4e38f, m1 = -3.4e38f, m2 = -3.4e38f, m3 = -3.4e38f;
    float s0 = 0.f, s1 = 0.f, s2 = 0.f, s3 = 0.f;

    for (int t = 0; t < Nn/8; t += 4){
        float vv[4];
#pragma unroll
        for (int j = 0; j < 4; j++){
            int n = nr + (t + j) * 8;
            float xv = x[cb + (size_t)n * Dd];
            float g = lg2(fmaf(s_q[n], pd, EPSc));
            vv[j] = fmaf(al, xv, fmaf(be, g, Ad + s_B[n]));
        }
        // 4 independent branchless chains
        float nm;
        nm = fmaxf(m0, vv[0]); s0 = fmaf(s0, ex2(m0-nm), ex2(vv[0]-nm)); m0 = nm;
        nm = fmaxf(m1, vv[1]); s1 = fmaf(s1, ex2(m1-nm), ex2(vv[1]-nm)); m1 = nm;
        nm = fmaxf(m2, vv[2]); s2 = fmaf(s2, ex2(m2-nm), ex2(vv[2]-nm)); m2 = nm;
        nm = fmaxf(m3, vv[3]); s3 = fmaf(s3, ex2(m3-nm), ex2(vv[3]-nm)); m3 = nm;
    }
    // merge the 4 chains
    float nm;
    nm = fmaxf(m0, m1); s0 = s0*ex2(m0-nm) + s1*ex2(m1-nm); m0 = nm;
    nm = fmaxf(m2, m3); s2 = s2*ex2(m2-nm) + s3*ex2(m3-nm); m2 = nm;
    nm = fmaxf(m0, m2); s0 = s0*ex2(m0-nm) + s2*ex2(m2-nm); m0 = nm;

    s_m[tid] = m0; s_s[tid] = s0;
    __syncthreads();
    if (tid < 32){
        float M = s_m[tid], S = s_s[tid];
#pragma unroll
        for (int j = 1; j < 8; j++){
            float M2 = s_m[j*32 + tid], S2 = s_s[j*32 + tid];
            float w = fmaxf(M, M2);
            S = S*ex2(M - w) + S2*ex2(M2 - w);
            M = w;
        }
        g_Lc[k][b*Dd + blockIdx.x*32 + tid] = M + lg2(S);
    }
}

// ---------------------------------------------------------------------------
// Fused iteration kernel (block-per-row). MODE = k in {0,1,2}.
// All scalar constants preloaded from g_sc — no divisions in the hot path.
// ---------------------------------------------------------------------------
template<int MODE>
__global__ void __launch_bounds__(128) fused_kernel(
    const float* __restrict__ x, const float* __restrict__ p0,
    const float* __restrict__ q0, const float* __restrict__ mask,
    float* __restrict__ out)
{
    __shared__ float sm_m[4], sm_s[4];
    const int k = MODE;
    int row = blockIdx.x, b = row >> 10;
    int tid = threadIdx.x, wid = tid >> 5, lane = tid & 31;
    size_t base = (size_t)row * Dd;

    float invrk2 = g_sc[k][0];
    float il2sk  = g_sc[k][1];
    float rkdsk  = g_sc[k][2];
    float invrn2 = g_sc[k][3];
    float rk     = g_sc[k][4];
    float mk = __ldg(mask + row);
    float e2 = g_e[k][row];
    float q  = __ldg(q0 + row);
    float rkm = rk * mk;

    float Brow = 0.f, al = 0.f, be = 0.f, skdrk = 0.f, Lr0 = 0.f;
    if (MODE == 0){
        Lr0 = g_Lrow[0][row];
    } else {
        Brow  = g_B[k][row];
        skdrk = g_sc[k][5];
        al    = g_sc[k][8];
        be    = g_sc[k][9];
    }

    float4 xv = ((const float4*)(x + base))[tid];
    float4 pv = ((const float4*)(p0 + (size_t)b*Dd))[tid];
    float4 Lc = ((const float4*)(g_Lc[k] + (size_t)b*Dd))[tid];
    float4 zv = make_float4(0.f,0.f,0.f,0.f);
    if (MODE != 0) zv = ((const float4*)(g_z + base))[tid];

    float4 gv;
    gv.x = lg2(fmaf(q, pv.x, EPSc));
    gv.y = lg2(fmaf(q, pv.y, EPSc));
    gv.z = lg2(fmaf(q, pv.z, EPSc));
    gv.w = lg2(fmaf(q, pv.w, EPSc));

    float4 lt;
    if (MODE == 0){
        float4 m0 = ((const float4*)(g_m[0] + (size_t)b*Dd))[tid];
        lt.x = m0.x + fmaf(xv.x, invrk2, gv.x) - Lr0;
        lt.y = m0.y + fmaf(xv.y, invrk2, gv.y) - Lr0;
        lt.z = m0.z + fmaf(xv.z, invrk2, gv.z) - Lr0;
        lt.w = m0.w + fmaf(xv.w, invrk2, gv.w) - Lr0;
    } else {
        float4 Av = ((const float4*)(g_A[k] + (size_t)b*Dd))[tid];
        lt.x = (xv.x - zv.x)*invrk2 + fmaf(al, xv.x, fmaf(be, gv.x, skdrk*(Av.x + Brow)));
        lt.y = (xv.y - zv.y)*invrk2 + fmaf(al, xv.y, fmaf(be, gv.y, skdrk*(Av.y + Brow)));
        lt.z = (xv.z - zv.z)*invrk2 + fmaf(al, xv.z, fmaf(be, gv.z, skdrk*(Av.z + Brow)));
        lt.w = (xv.w - zv.w)*invrk2 + fmaf(al, xv.w, fmaf(be, gv.w, skdrk*(Av.w + Brow)));
    }

    float4 y, zn;
    {
        float U, ls;
        U = fmaf(zv.x, il2sk, lt.x*rkdsk);  ls = e2 - Lc.x + U;
        zn.x = fmaf(rkm, ex2(lt.x) - ex2(ls), zv.x);
        y.x  = fmaf(xv.x - zn.x, invrn2, ls);
        U = fmaf(zv.y, il2sk, lt.y*rkdsk);  ls = e2 - Lc.y + U;
        zn.y = fmaf(rkm, ex2(lt.y) - ex2(ls), zv.y);
        y.y  = fmaf(xv.y - zn.y, invrn2, ls);
        U = fmaf(zv.z, il2sk, lt.z*rkdsk);  ls = e2 - Lc.z + U;
        zn.z = fmaf(rkm, ex2(lt.z) - ex2(ls), zv.z);
        y.z  = fmaf(xv.z - zn.z, invrn2, ls);
        U = fmaf(zv.w, il2sk, lt.w*rkdsk);  ls = e2 - Lc.w + U;
        zn.w = fmaf(rkm, ex2(lt.w) - ex2(ls), zv.w);
        y.w  = fmaf(xv.w - zn.w, invrn2, ls);
    }

    // one-barrier block LSE over y (512 values)
    float mx = fmaxf(fmaxf(y.x, y.y), fmaxf(y.z, y.w));
    mx = warpMax(mx);
    float se = ex2(y.x-mx) + ex2(y.y-mx) + ex2(y.z-mx) + ex2(y.w-mx);
    se = warpSum(se);
    if (lane == 0){ sm_m[wid] = mx; sm_s[wid] = se; }
    __syncthreads();
    float M0 = sm_m[0], M1 = sm_m[1], M2v = sm_m[2], M3 = sm_m[3];
    float Mf = fmaxf(fmaxf(M0, M1), fmaxf(M2v, M3));
    float Sf = sm_s[0]*ex2(M0-Mf) + sm_s[1]*ex2(M1-Mf)
             + sm_s[2]*ex2(M2v-Mf) + sm_s[3]*ex2(M3-Mf);
    float L2 = Mf + lg2(Sf);

    if (MODE == 2){
        float4 m3 = ((const float4*)(g_m[3] + (size_t)b*Dd))[tid];
        float4 o;
        o.x = ex2(m3.x + y.x - L2)*mk;
        o.y = ex2(m3.y + y.y - L2)*mk;
        o.z = ex2(m3.z + y.z - L2)*mk;
        o.w = ex2(m3.w + y.w - L2)*mk;
        ((float4*)(out + base))[tid] = o;
    } else {
        ((float4*)(g_z + base))[tid] = zn;
        if (tid == 0) g_Lrow[k+1][row] = L2;
    }
}

// ---------------------------------------------------------------------------
extern "C" void kernel_launch(void* const* d_in, const int* in_sizes, int n_in,
                              void* d_out, int out_size)
{
    const float* x    = (const float*)d_in[0];
    const float* p0   = (const float*)d_in[1];
    const float* q0   = (const float*)d_in[2];
    const float* a1   = (const float*)d_in[3];
    const float* a2   = (const float*)d_in[4];
    const float* a3   = (const float*)d_in[5];
    const float* rho  = (const float*)d_in[6];
    const float* mask = (const float*)d_in[7];
    float* out = (float*)d_out;

    precomp_kernel<<<Bb, 512>>>(p0, q0, a2, a3, rho);
    row0lse_kernel<<<Bb*Nn/8, 256>>>(x, p0, q0);

    dim3 cgrid(Dd / 32, Bb);

    tables_kernel<<<Bb, 512>>>(rho, a1, 0);
    colred_kernel<<<cgrid, 256>>>(x, p0, q0, 0);
    fused_kernel<0><<<Bb*Nn, 128>>>(x, p0, q0, mask, out);

    tables_kernel<<<Bb, 512>>>(rho, a1, 1);
    colred_kernel<<<cgrid, 256>>>(x, p0, q0, 1);
    fused_kernel<1><<<Bb*Nn, 128>>>(x, p0, q0, mask, out);

    tables_kernel<<<Bb, 512>>>(rho, a1, 2);
    colred_kernel<<<cgrid, 256>>>(x, p0, q0, 2);
    fused_kernel<2><<<Bb*Nn, 128>>>(x, p0, q0, mask, out);
}

// round 9
// speedup vs baseline: 2.3186x; 1.0206x over previous
#include <cuda_runtime.h>
#include <math.h>

#define Bb 64
#define Nn 1024
#define Dd 512
#define TOT (Bb*Nn*Dd)
#define NUMIT 4
#define EPSc 1e-8f
#define LOG2E 1.44269504088896340736f
#define LN2f  0.69314718055994530942f

// Scratch (device globals). All log-domain state in BASE 2.
// Per-element state is ONLY z (B,N,D). The dual u is a closed form:
//   U_k = alpha_k*x + beta_k*g + A_k[b,d] + B_k[b,n],  g = lg2(q0*p0+eps)
__device__ float g_z[TOT];
__device__ float g_m[NUMIT][Bb*Dd];        // log2_mu stage k
__device__ float g_e[NUMIT][Bb*Nn];        // log2_eta stage k
__device__ float g_A[3][Bb*Dd];            // U-decomposition (b,d) table
__device__ float g_B[3][Bb*Nn];            // U-decomposition (b,n) table
__device__ float g_Lc[3][Bb*Dd];           // base-2 col-LSE of U_k
__device__ float g_Lrow[3][Bb*Nn];         // base-2 row-LSE stage k
__device__ float g_sc[3][10];              // per-iteration scalar constants
__device__ float g_invr0l2;                // 1/(rho0*ln2)

// g_sc layout: 0:1/(rk ln2)  1:1/(ln2 sk)  2:rk/sk  3:1/(rn ln2)  4:rk
//              5:sk/rk       6:al_k        7:be_k   8:al_{k-1}    9:be_{k-1}

__device__ __forceinline__ float ex2(float v){
    float r; asm("ex2.approx.ftz.f32 %0, %1;" : "=f"(r) : "f"(v)); return r;
}
__device__ __forceinline__ float lg2(float v){
    float r; asm("lg2.approx.ftz.f32 %0, %1;" : "=f"(r) : "f"(v)); return r;
}
__device__ __forceinline__ float warpMax(float v){
#pragma unroll
    for (int o = 16; o > 0; o >>= 1) v = fmaxf(v, __shfl_xor_sync(0xffffffffu, v, o));
    return v;
}
__device__ __forceinline__ float warpSum(float v){
#pragma unroll
    for (int o = 16; o > 0; o >>= 1) v += __shfl_xor_sync(0xffffffffu, v, o);
    return v;
}

// ---------------------------------------------------------------------------
// Precompute log2_mu / log2_eta trajectories (dual marginals separable).
// ---------------------------------------------------------------------------
__global__ void __launch_bounds__(512) precomp_kernel(
    const float* __restrict__ p0, const float* __restrict__ q0,
    const float* __restrict__ a2, const float* __restrict__ a3,
    const float* __restrict__ rho)
{
    __shared__ float red[32];
    int b = blockIdx.x, tid = threadIdx.x;
    int wid = tid >> 5, lane = tid & 31;

    if (b == 0 && tid == 0) g_invr0l2 = 1.f / (rho[0] * LN2f);

    float lp = logf(p0[b*Dd + tid]);
    float m = lp, A = 0.f;
    g_m[0][b*Dd + tid] = lp * LOG2E;
    for (int kk = 0; kk < NUMIT-1; kk++){
        float r = rho[kk], a = a2[kk];
        float g = (r*m + a*lp - A) / (r + a);
        float v = warpMax(g);
        if (lane == 0) red[wid] = v;
        __syncthreads();
        if (wid == 0){ float u = (lane < 16) ? red[lane] : -3.4e38f; u = warpMax(u); if (lane==0) red[16]=u; }
        __syncthreads();
        float mx = red[16];
        __syncthreads();
        float s = warpSum(expf(g - mx));
        if (lane == 0) red[wid] = s;
        __syncthreads();
        if (wid == 0){ float u = (lane < 16) ? red[lane] : 0.f; u = warpSum(u); if (lane==0) red[16]=u; }
        __syncthreads();
        float L = mx + logf(red[16]);
        __syncthreads();
        m = g - L;
        A += r * expf(m);
        g_m[kk+1][b*Dd + tid] = m * LOG2E;
    }

    float lq0 = logf(q0[b*Nn + tid] + EPSc);
    float lq1 = logf(q0[b*Nn + tid + 512] + EPSc);
    float e0 = lq0, e1 = lq1, C0 = 0.f, C1 = 0.f;
    g_e[0][b*Nn + tid]       = e0 * LOG2E;
    g_e[0][b*Nn + tid + 512] = e1 * LOG2E;
    for (int kk = 0; kk < NUMIT-1; kk++){
        float r = rho[kk], a = a3[kk];
        float h0 = (r*e0 + a*lq0 - C0) / (r + a);
        float h1 = (r*e1 + a*lq1 - C1) / (r + a);
        float v = warpMax(fmaxf(h0, h1));
        if (lane == 0) red[wid] = v;
        __syncthreads();
        if (wid == 0){ float u = (lane < 16) ? red[lane] : -3.4e38f; u = warpMax(u); if (lane==0) red[16]=u; }
        __syncthreads();
        float mx = red[16];
        __syncthreads();
        float s = warpSum(expf(h0 - mx) + expf(h1 - mx));
        if (lane == 0) red[wid] = s;
        __syncthreads();
        if (wid == 0){ float u = (lane < 16) ? red[lane] : 0.f; u = warpSum(u); if (lane==0) red[16]=u; }
        __syncthreads();
        float L = mx + logf(red[16]);
        __syncthreads();
        e0 = h0 - L; e1 = h1 - L;
        C0 += r * expf(e0); C1 += r * expf(e1);
        g_e[kk+1][b*Nn + tid]       = e0 * LOG2E;
        g_e[kk+1][b*Nn + tid + 512] = e1 * LOG2E;
    }
}

// ---------------------------------------------------------------------------
// Iteration-0 row LSE (base-2), warp-per-row: Lrow_0 = lse2_d(x/(r0 ln2) + g)
// ---------------------------------------------------------------------------
__global__ void __launch_bounds__(256) row0lse_kernel(
    const float* __restrict__ x, const float* __restrict__ p0,
    const float* __restrict__ q0)
{
    int lane = threadIdx.x & 31;
    int row  = blockIdx.x * 8 + (threadIdx.x >> 5);
    int b = row >> 10;
    const float4* x4 = (const float4*)(x + (size_t)row * Dd);
    const float4* p4 = (const float4*)(p0 + (size_t)b * Dd);
    float invr2 = g_invr0l2;
    float q = __ldg(q0 + row);

    float4 y[4];
    float mx = -3.4e38f;
#pragma unroll
    for (int i = 0; i < 4; i++){
        int c = i*32 + lane;
        float4 xv = __ldcs(&x4[c]);
        float4 pv = p4[c];
        y[i].x = fmaf(xv.x, invr2, lg2(fmaf(q, pv.x, EPSc)));
        y[i].y = fmaf(xv.y, invr2, lg2(fmaf(q, pv.y, EPSc)));
        y[i].z = fmaf(xv.z, invr2, lg2(fmaf(q, pv.z, EPSc)));
        y[i].w = fmaf(xv.w, invr2, lg2(fmaf(q, pv.w, EPSc)));
        mx = fmaxf(mx, fmaxf(fmaxf(y[i].x, y[i].y), fmaxf(y[i].z, y[i].w)));
    }
    mx = warpMax(mx);
    float se = 0.f;
#pragma unroll
    for (int i = 0; i < 4; i++)
        se += ex2(y[i].x-mx) + ex2(y[i].y-mx) + ex2(y[i].z-mx) + ex2(y[i].w-mx);
    se = warpSum(se);
    if (lane == 0) g_Lrow[0][row] = mx + lg2(se);
}

// ---------------------------------------------------------------------------
// Table + scalar maintenance (tiny).
// ---------------------------------------------------------------------------
__global__ void __launch_bounds__(512) tables_kernel(
    const float* __restrict__ rho, const float* __restrict__ a1, int k)
{
    int b = blockIdx.x, tid = threadIdx.x;
    float rk = rho[k];
    float f = rk / (a1[k] + rk);

    if (b == 0 && tid == 0){
        float sk = a1[k] + rk;
        float rn = rho[k+1];
        g_sc[k][0] = 1.f / (rk * LN2f);
        g_sc[k][1] = 1.f / (LN2f * sk);
        g_sc[k][2] = rk / sk;
        g_sc[k][3] = 1.f / (rn * LN2f);
        g_sc[k][4] = rk;
        g_sc[k][5] = sk / rk;
        float s0 = a1[0] + rho[0];
        float al = 1.f/(s0*LN2f), be = rho[0]/s0;
        float alp = 0.f, bep = 0.f;
        for (int j = 1; j <= k; j++){
            alp = al; bep = be;
            float s = a1[j] + rho[j];
            al = (1.f/LN2f + rho[j]*al)/s;
            be = rho[j]*be/s;
        }
        g_sc[k][6] = al;  g_sc[k][7] = be;
        g_sc[k][8] = alp; g_sc[k][9] = bep;
    }

    int id = b*Dd + tid;
    if (k == 0){
        g_A[0][id] = f * g_m[0][id];
        int in0 = b*Nn + tid, in1 = in0 + 512;
        g_B[0][in0] = -f * g_Lrow[0][in0];
        g_B[0][in1] = -f * g_Lrow[0][in1];
    } else {
        g_A[k][id] = f * (g_A[k-1][id] - g_Lc[k-1][id] + g_m[k][id]);
        int in0 = b*Nn + tid, in1 = in0 + 512;
        g_B[k][in0] = f * (g_B[k-1][in0] + g_e[k-1][in0] - g_Lrow[k][in0]);
        g_B[k][in1] = f * (g_B[k-1][in1] + g_e[k-1][in1] - g_Lrow[k][in1]);
    }
}

// ---------------------------------------------------------------------------
// Col reduce (reads ONLY x, evict-first): Lc_k = lse2_n(U_k),
//   U_k = al*x + be*g + A_k[b,d] + B_k[b,n]
// 4 independent BRANCHY online-LSE chains (1 amortized ex2/value, rare
// rescale), batch-8 loads for MLP. x marked streaming so z stays in L2.
// ---------------------------------------------------------------------------
__global__ void __launch_bounds__(256) colred_kernel(
    const float* __restrict__ x, const float* __restrict__ p0,
    const float* __restrict__ q0, int k)
{
    __shared__ float s_m[256], s_s[256];
    __shared__ float s_q[Nn], s_B[Nn];

    int b = blockIdx.y, tid = threadIdx.x;
    int dc = tid & 31, nr = tid >> 5;
    int d = blockIdx.x * 32 + dc;

    float al = g_sc[k][6], be = g_sc[k][7];
    float pd = p0[b*Dd + d];
    float Ad = g_A[k][b*Dd + d];
    for (int i = tid; i < Nn; i += 256){
        s_q[i] = q0[b*Nn + i];
        s_B[i] = g_B[k][b*Nn + i];
    }
    __syncthreads();

    size_t cb = (size_t)b * Nn * Dd + d;
    float mm[4] = {-3.4e38f, -3.4e38f, -3.4e38f, -3.4e38f};
    float ss[4] = {0.f, 0.f, 0.f, 0.f};

    for (int t = 0; t < Nn/8; t += 8){
        float vv[8];
#pragma unroll
        for (int j = 0; j < 8; j++){
            int n = nr + (t + j) * 8;
            float xv = __ldcs(x + cb + (size_t)n * Dd);
            float g = lg2(fmaf(s_q[n], pd, EPSc));
            vv[j] = fmaf(al, xv, fmaf(be, g, Ad + s_B[n]));
        }
#pragma unroll
        for (int j = 0; j < 8; j++){
            int c = j & 3;
            float v = vv[j];
            if (v > mm[c]){ ss[c] = fmaf(ss[c], ex2(mm[c] - v), 1.f); mm[c] = v; }
            else          { ss[c] += ex2(v - mm[c]); }
        }
    }
    // merge the 4 chains
    float nm;
    nm = fmaxf(mm[0], mm[1]); ss[0] = ss[0]*ex2(mm[0]-nm) + ss[1]*ex2(mm[1]-nm); mm[0] = nm;
    nm = fmaxf(mm[2], mm[3]); ss[2] = ss[2]*ex2(mm[2]-nm) + ss[3]*ex2(mm[3]-nm); mm[2] = nm;
    nm = fmaxf(mm[0], mm[2]); ss[0] = ss[0]*ex2(mm[0]-nm) + ss[2]*ex2(mm[2]-nm); mm[0] = nm;

    s_m[tid] = mm[0]; s_s[tid] = ss[0];
    __syncthreads();
    if (tid < 32){
        float M = s_m[tid], S = s_s[tid];
#pragma unroll
        for (int j = 1; j < 8; j++){
            float M2 = s_m[j*32 + tid], S2 = s_s[j*32 + tid];
            float w = fmaxf(M, M2);
            S = S*ex2(M - w) + S2*ex2(M2 - w);
            M = w;
        }
        g_Lc[k][b*Dd + blockIdx.x*32 + tid] = M + lg2(S);
    }
}

// ---------------------------------------------------------------------------
// Fused iteration kernel (block-per-row). MODE = k in {0,1,2}.
// x reads are streaming (evict-first) so z survives in L2 across kernels.
// ---------------------------------------------------------------------------
template<int MODE>
__global__ void __launch_bounds__(128) fused_kernel(
    const float* __restrict__ x, const float* __restrict__ p0,
    const float* __restrict__ q0, const float* __restrict__ mask,
    float* __restrict__ out)
{
    __shared__ float sm_m[4], sm_s[4];
    const int k = MODE;
    int row = blockIdx.x, b = row >> 10;
    int tid = threadIdx.x, wid = tid >> 5, lane = tid & 31;
    size_t base = (size_t)row * Dd;

    float invrk2 = g_sc[k][0];
    float il2sk  = g_sc[k][1];
    float rkdsk  = g_sc[k][2];
    float invrn2 = g_sc[k][3];
    float rk     = g_sc[k][4];
    float mk = __ldg(mask + row);
    float e2 = g_e[k][row];
    float q  = __ldg(q0 + row);
    float rkm = rk * mk;

    float Brow = 0.f, al = 0.f, be = 0.f, skdrk = 0.f, Lr0 = 0.f;
    if (MODE == 0){
        Lr0 = g_Lrow[0][row];
    } else {
        Brow  = g_B[k][row];
        skdrk = g_sc[k][5];
        al    = g_sc[k][8];
        be    = g_sc[k][9];
    }

    float4 xv = __ldcs(&((const float4*)(x + base))[tid]);
    float4 pv = ((const float4*)(p0 + (size_t)b*Dd))[tid];
    float4 Lc = ((const float4*)(g_Lc[k] + (size_t)b*Dd))[tid];
    float4 zv = make_float4(0.f,0.f,0.f,0.f);
    if (MODE != 0) zv = ((const float4*)(g_z + base))[tid];

    float4 gv;
    gv.x = lg2(fmaf(q, pv.x, EPSc));
    gv.y = lg2(fmaf(q, pv.y, EPSc));
    gv.z = lg2(fmaf(q, pv.z, EPSc));
    gv.w = lg2(fmaf(q, pv.w, EPSc));

    float4 lt;
    if (MODE == 0){
        float4 m0 = ((const float4*)(g_m[0] + (size_t)b*Dd))[tid];
        lt.x = m0.x + fmaf(xv.x, invrk2, gv.x) - Lr0;
        lt.y = m0.y + fmaf(xv.y, invrk2, gv.y) - Lr0;
        lt.z = m0.z + fmaf(xv.z, invrk2, gv.z) - Lr0;
        lt.w = m0.w + fmaf(xv.w, invrk2, gv.w) - Lr0;
    } else {
        float4 Av = ((const float4*)(g_A[k] + (size_t)b*Dd))[tid];
        lt.x = (xv.x - zv.x)*invrk2 + fmaf(al, xv.x, fmaf(be, gv.x, skdrk*(Av.x + Brow)));
        lt.y = (xv.y - zv.y)*invrk2 + fmaf(al, xv.y, fmaf(be, gv.y, skdrk*(Av.y + Brow)));
        lt.z = (xv.z - zv.z)*invrk2 + fmaf(al, xv.z, fmaf(be, gv.z, skdrk*(Av.z + Brow)));
        lt.w = (xv.w - zv.w)*invrk2 + fmaf(al, xv.w, fmaf(be, gv.w, skdrk*(Av.w + Brow)));
    }

    float4 y, zn;
    {
        float U, ls;
        U = fmaf(zv.x, il2sk, lt.x*rkdsk);  ls = e2 - Lc.x + U;
        zn.x = fmaf(rkm, ex2(lt.x) - ex2(ls), zv.x);
        y.x  = fmaf(xv.x - zn.x, invrn2, ls);
        U = fmaf(zv.y, il2sk, lt.y*rkdsk);  ls = e2 - Lc.y + U;
        zn.y = fmaf(rkm, ex2(lt.y) - ex2(ls), zv.y);
        y.y  = fmaf(xv.y - zn.y, invrn2, ls);
        U = fmaf(zv.z, il2sk, lt.z*rkdsk);  ls = e2 - Lc.z + U;
        zn.z = fmaf(rkm, ex2(lt.z) - ex2(ls), zv.z);
        y.z  = fmaf(xv.z - zn.z, invrn2, ls);
        U = fmaf(zv.w, il2sk, lt.w*rkdsk);  ls = e2 - Lc.w + U;
        zn.w = fmaf(rkm, ex2(lt.w) - ex2(ls), zv.w);
        y.w  = fmaf(xv.w - zn.w, invrn2, ls);
    }

    // one-barrier block LSE over y (512 values)
    float mx = fmaxf(fmaxf(y.x, y.y), fmaxf(y.z, y.w));
    mx = warpMax(mx);
    float se = ex2(y.x-mx) + ex2(y.y-mx) + ex2(y.z-mx) + ex2(y.w-mx);
    se = warpSum(se);
    if (lane == 0){ sm_m[wid] = mx; sm_s[wid] = se; }
    __syncthreads();
    float M0 = sm_m[0], M1 = sm_m[1], M2v = sm_m[2], M3 = sm_m[3];
    float Mf = fmaxf(fmaxf(M0, M1), fmaxf(M2v, M3));
    float Sf = sm_s[0]*ex2(M0-Mf) + sm_s[1]*ex2(M1-Mf)
             + sm_s[2]*ex2(M2v-Mf) + sm_s[3]*ex2(M3-Mf);
    float L2 = Mf + lg2(Sf);

    if (MODE == 2){
        float4 m3 = ((const float4*)(g_m[3] + (size_t)b*Dd))[tid];
        float4 o;
        o.x = ex2(m3.x + y.x - L2)*mk;
        o.y = ex2(m3.y + y.y - L2)*mk;
        o.z = ex2(m3.z + y.z - L2)*mk;
        o.w = ex2(m3.w + y.w - L2)*mk;
        __stcs(&((float4*)(out + base))[tid], o);
    } else {
        ((float4*)(g_z + base))[tid] = zn;
        if (tid == 0) g_Lrow[k+1][row] = L2;
    }
}

// ---------------------------------------------------------------------------
extern "C" void kernel_launch(void* const* d_in, const int* in_sizes, int n_in,
                              void* d_out, int out_size)
{
    const float* x    = (const float*)d_in[0];
    const float* p0   = (const float*)d_in[1];
    const float* q0   = (const float*)d_in[2];
    const float* a1   = (const float*)d_in[3];
    const float* a2   = (const float*)d_in[4];
    const float* a3   = (const float*)d_in[5];
    const float* rho  = (const float*)d_in[6];
    const float* mask = (const float*)d_in[7];
    float* out = (float*)d_out;

    precomp_kernel<<<Bb, 512>>>(p0, q0, a2, a3, rho);
    row0lse_kernel<<<Bb*Nn/8, 256>>>(x, p0, q0);

    dim3 cgrid(Dd / 32, Bb);

    tables_kernel<<<Bb, 512>>>(rho, a1, 0);
    colred_kernel<<<cgrid, 256>>>(x, p0, q0, 0);
    fused_kernel<0><<<Bb*Nn, 128>>>(x, p0, q0, mask, out);

    tables_kernel<<<Bb, 512>>>(rho, a1, 1);
    colred_kernel<<<cgrid, 256>>>(x, p0, q0, 1);
    fused_kernel<1><<<Bb*Nn, 128>>>(x, p0, q0, mask, out);

    tables_kernel<<<Bb, 512>>>(rho, a1, 2);
    colred_kernel<<<cgrid, 256>>>(x, p0, q0, 2);
    fused_kernel<2><<<Bb*Nn, 128>>>(x, p0, q0, mask, out);
}

// round 10
// speedup vs baseline: 2.3974x; 1.0340x over previous
#include <cuda_runtime.h>
#include <math.h>

#define Bb 64
#define Nn 1024
#define Dd 512
#define TOT (Bb*Nn*Dd)
#define NUMIT 4
#define EPSc 1e-8f
#define LOG2E 1.44269504088896340736f
#define LN2f  0.69314718055994530942f
#define CH 64          // chunks per batch
#define RPB 16         // rows per block (Nn / CH)

// Scratch (device globals). All log-domain state in BASE 2.
// Per-element state is ONLY z. U_k = closed form; col-LSE partials are
// accumulated inside the row kernels (g_Sp) -> no separate colred pass.
__device__ float g_z[TOT];
__device__ float g_m[NUMIT][Bb*Dd];        // log2_mu stage k
__device__ float g_e[NUMIT][Bb*Nn];        // log2_eta stage k
__device__ float g_A[3][Bb*Dd];            // U-decomposition (b,d) table
__device__ float g_B[3][Bb*Nn];            // U-decomposition (b,n) table
__device__ float g_Lc[3][Bb*Dd];           // base-2 col-LSE of U_k
__device__ float g_Lrow[3][Bb*Nn];         // base-2 row-LSE stage k
__device__ float g_sc[3][10];              // per-iteration scalar constants
__device__ float g_Sp[Bb*CH*Dd];           // per-chunk col partial sums

// g_sc layout: 0:1/(rk ln2)  1:1/(ln2 sk)  2:rk/sk  3:1/(rn ln2)  4:rk
//              5:sk/rk       6:al_k        7:be_k   8:al_{k-1}    9:be_{k-1}

__device__ __forceinline__ float ex2(float v){
    float r; asm("ex2.approx.ftz.f32 %0, %1;" : "=f"(r) : "f"(v)); return r;
}
__device__ __forceinline__ float lg2(float v){
    float r; asm("lg2.approx.ftz.f32 %0, %1;" : "=f"(r) : "f"(v)); return r;
}
__device__ __forceinline__ float warpMax(float v){
#pragma unroll
    for (int o = 16; o > 0; o >>= 1) v = fmaxf(v, __shfl_xor_sync(0xffffffffu, v, o));
    return v;
}
__device__ __forceinline__ float warpSum(float v){
#pragma unroll
    for (int o = 16; o > 0; o >>= 1) v += __shfl_xor_sync(0xffffffffu, v, o);
    return v;
}

// ---------------------------------------------------------------------------
// Precompute log2_mu / log2_eta trajectories + ALL scalar constants.
// ---------------------------------------------------------------------------
__global__ void __launch_bounds__(512) precomp_kernel(
    const float* __restrict__ p0, const float* __restrict__ q0,
    const float* __restrict__ a2, const float* __restrict__ a3,
    const float* __restrict__ rho, const float* __restrict__ a1)
{
    __shared__ float red[32];
    int b = blockIdx.x, tid = threadIdx.x;
    int wid = tid >> 5, lane = tid & 31;

    if (b == 0 && tid == 0){
        for (int k = 0; k < 3; k++){
            float rk = rho[k];
            float sk = a1[k] + rk;
            float rn = rho[k+1];
            g_sc[k][0] = 1.f / (rk * LN2f);
            g_sc[k][1] = 1.f / (LN2f * sk);
            g_sc[k][2] = rk / sk;
            g_sc[k][3] = 1.f / (rn * LN2f);
            g_sc[k][4] = rk;
            g_sc[k][5] = sk / rk;
            float s0 = a1[0] + rho[0];
            float al = 1.f/(s0*LN2f), be = rho[0]/s0;
            float alp = 0.f, bep = 0.f;
            for (int j = 1; j <= k; j++){
                alp = al; bep = be;
                float s = a1[j] + rho[j];
                al = (1.f/LN2f + rho[j]*al)/s;
                be = rho[j]*be/s;
            }
            g_sc[k][6] = al;  g_sc[k][7] = be;
            g_sc[k][8] = alp; g_sc[k][9] = bep;
        }
    }

    float lp = logf(p0[b*Dd + tid]);
    float m = lp, A = 0.f;
    g_m[0][b*Dd + tid] = lp * LOG2E;
    for (int kk = 0; kk < NUMIT-1; kk++){
        float r = rho[kk], a = a2[kk];
        float g = (r*m + a*lp - A) / (r + a);
        float v = warpMax(g);
        if (lane == 0) red[wid] = v;
        __syncthreads();
        if (wid == 0){ float u = (lane < 16) ? red[lane] : -3.4e38f; u = warpMax(u); if (lane==0) red[16]=u; }
        __syncthreads();
        float mx = red[16];
        __syncthreads();
        float s = warpSum(expf(g - mx));
        if (lane == 0) red[wid] = s;
        __syncthreads();
        if (wid == 0){ float u = (lane < 16) ? red[lane] : 0.f; u = warpSum(u); if (lane==0) red[16]=u; }
        __syncthreads();
        float L = mx + logf(red[16]);
        __syncthreads();
        m = g - L;
        A += r * expf(m);
        g_m[kk+1][b*Dd + tid] = m * LOG2E;
    }

    float lq0 = logf(q0[b*Nn + tid] + EPSc);
    float lq1 = logf(q0[b*Nn + tid + 512] + EPSc);
    float e0 = lq0, e1 = lq1, C0 = 0.f, C1 = 0.f;
    g_e[0][b*Nn + tid]       = e0 * LOG2E;
    g_e[0][b*Nn + tid + 512] = e1 * LOG2E;
    for (int kk = 0; kk < NUMIT-1; kk++){
        float r = rho[kk], a = a3[kk];
        float h0 = (r*e0 + a*lq0 - C0) / (r + a);
        float h1 = (r*e1 + a*lq1 - C1) / (r + a);
        float v = warpMax(fmaxf(h0, h1));
        if (lane == 0) red[wid] = v;
        __syncthreads();
        if (wid == 0){ float u = (lane < 16) ? red[lane] : -3.4e38f; u = warpMax(u); if (lane==0) red[16]=u; }
        __syncthreads();
        float mx = red[16];
        __syncthreads();
        float s = warpSum(expf(h0 - mx) + expf(h1 - mx));
        if (lane == 0) red[wid] = s;
        __syncthreads();
        if (wid == 0){ float u = (lane < 16) ? red[lane] : 0.f; u = warpSum(u); if (lane==0) red[16]=u; }
        __syncthreads();
        float L = mx + logf(red[16]);
        __syncthreads();
        e0 = h0 - L; e1 = h1 - L;
        C0 += r * expf(e0); C1 += r * expf(e1);
        g_e[kk+1][b*Nn + tid]       = e0 * LOG2E;
        g_e[kk+1][b*Nn + tid + 512] = e1 * LOG2E;
    }
}

// ---------------------------------------------------------------------------
// Row-0 LSE + col-partial accumulation. Block = 16 consecutive rows of one
// batch (128 threads; thread owns d = 4*tid..4*tid+3 for every row).
//   Lrow_0[row] = lse2_d(x/(r0 ln2) + g);  Sp[b,chunk,d] = sum_rows 2^(f0*lt0)
// ---------------------------------------------------------------------------
__global__ void __launch_bounds__(128) row0lse_kernel(
    const float* __restrict__ x, const float* __restrict__ p0,
    const float* __restrict__ q0)
{
    __shared__ float sm_m[2][4], sm_s[2][4];
    int bc = blockIdx.x;
    int b = bc >> 6, chunk = bc & 63;
    int tid = threadIdx.x, wid = tid >> 5, lane = tid & 31;

    float invr2 = g_sc[0][0];
    float f0    = g_sc[0][2];
    float4 pv = ((const float4*)(p0 + (size_t)b*Dd))[tid];
    float4 m0 = ((const float4*)(g_m[0] + (size_t)b*Dd))[tid];
    float4 acc = make_float4(0.f,0.f,0.f,0.f);

    int row0 = b*Nn + chunk*RPB;
#pragma unroll 2
    for (int r = 0; r < RPB; r++){
        int row = row0 + r;
        size_t base = (size_t)row * Dd;
        float q = __ldg(q0 + row);
        float4 xv = __ldcs(&((const float4*)(x + base))[tid]);
        float4 y;
        y.x = fmaf(xv.x, invr2, lg2(fmaf(q, pv.x, EPSc)));
        y.y = fmaf(xv.y, invr2, lg2(fmaf(q, pv.y, EPSc)));
        y.z = fmaf(xv.z, invr2, lg2(fmaf(q, pv.z, EPSc)));
        y.w = fmaf(xv.w, invr2, lg2(fmaf(q, pv.w, EPSc)));

        float mx = fmaxf(fmaxf(y.x, y.y), fmaxf(y.z, y.w));
        mx = warpMax(mx);
        float se = ex2(y.x-mx) + ex2(y.y-mx) + ex2(y.z-mx) + ex2(y.w-mx);
        se = warpSum(se);
        int pb = r & 1;
        if (lane == 0){ sm_m[pb][wid] = mx; sm_s[pb][wid] = se; }
        __syncthreads();
        float M0 = sm_m[pb][0], M1 = sm_m[pb][1], M2 = sm_m[pb][2], M3 = sm_m[pb][3];
        float Mf = fmaxf(fmaxf(M0, M1), fmaxf(M2, M3));
        float Sf = sm_s[pb][0]*ex2(M0-Mf) + sm_s[pb][1]*ex2(M1-Mf)
                 + sm_s[pb][2]*ex2(M2-Mf) + sm_s[pb][3]*ex2(M3-Mf);
        float L = Mf + lg2(Sf);
        if (tid == 0) g_Lrow[0][row] = L;

        // U0 = f0 * lt0, lt0 = m0 + y - L   (U0 <= 0, safe without offset)
        acc.x += ex2(f0*(m0.x + y.x - L));
        acc.y += ex2(f0*(m0.y + y.y - L));
        acc.z += ex2(f0*(m0.z + y.z - L));
        acc.w += ex2(f0*(m0.w + y.w - L));
    }
    ((float4*)(g_Sp + (size_t)bc*Dd))[tid] = acc;
}

// ---------------------------------------------------------------------------
// Tables: Lc_k from chunk partials; A_k, B_k recursion. Grid Bb x 512.
// ---------------------------------------------------------------------------
__global__ void __launch_bounds__(512) tables_kernel(
    const float* __restrict__ rho, const float* __restrict__ a1, int k)
{
    int b = blockIdx.x, tid = threadIdx.x;
    int id = b*Dd + tid;

    float S = 0.f;
#pragma unroll 8
    for (int c = 0; c < CH; c++)
        S += g_Sp[(size_t)(b*CH + c)*Dd + tid];
    float Lprev = (k == 0) ? 0.f : g_Lc[k-1][id];
    float Lck = Lprev + lg2(S);
    g_Lc[k][id] = Lck;

    float rk = rho[k];
    float f = rk / (a1[k] + rk);
    if (k == 0){
        g_A[0][id] = f * g_m[0][id];
        int in0 = b*Nn + tid, in1 = in0 + 512;
        g_B[0][in0] = -f * g_Lrow[0][in0];
        g_B[0][in1] = -f * g_Lrow[0][in1];
    } else {
        g_A[k][id] = f * (g_A[k-1][id] - g_Lc[k-1][id] + g_m[k][id]);
        int in0 = b*Nn + tid, in1 = in0 + 512;
        g_B[k][in0] = f * (g_B[k-1][in0] + g_e[k-1][in0] - g_Lrow[k][in0]);
        g_B[k][in1] = f * (g_B[k-1][in1] + g_e[k-1][in1] - g_Lrow[k][in1]);
    }
}

// ---------------------------------------------------------------------------
// Fused iteration kernel. Block = 16 consecutive rows (128 thr). MODE = k.
// Does: col-k finalize + row-(k+1) update + col-(k+1) partial accumulation.
// MODE 0: z=0, lt recomputed; MODE 1: generic; MODE 2: writes final output.
// ---------------------------------------------------------------------------
template<int MODE>
__global__ void __launch_bounds__(128) fused_kernel(
    const float* __restrict__ x, const float* __restrict__ p0,
    const float* __restrict__ q0, const float* __restrict__ mask,
    float* __restrict__ out)
{
    __shared__ float sm_m[2][4], sm_s[2][4];
    const int k = MODE;
    int bc = blockIdx.x;
    int b = bc >> 6, chunk = bc & 63;
    int tid = threadIdx.x, wid = tid >> 5, lane = tid & 31;

    float invrk2 = g_sc[k][0];
    float il2sk  = g_sc[k][1];
    float rkdsk  = g_sc[k][2];
    float invrn2 = g_sc[k][3];
    float rk     = g_sc[k][4];
    float al = 0.f, be = 0.f, skdrk = 0.f;
    float il2sn = 0.f, rndsn = 0.f;
    if (MODE != 0){
        skdrk = g_sc[k][5];
        al    = g_sc[k][8];
        be    = g_sc[k][9];
    }
    if (MODE != 2){
        il2sn = g_sc[k+1][1];
        rndsn = g_sc[k+1][2];
    }

    float4 pv = ((const float4*)(p0 + (size_t)b*Dd))[tid];
    float4 Lc = ((const float4*)(g_Lc[k] + (size_t)b*Dd))[tid];
    float4 mn = ((const float4*)(g_m[k+1] + (size_t)b*Dd))[tid];
    float4 AorM;   // MODE 0: m0 ; else: A_k
    if (MODE == 0) AorM = ((const float4*)(g_m[0] + (size_t)b*Dd))[tid];
    else           AorM = ((const float4*)(g_A[k] + (size_t)b*Dd))[tid];

    float4 acc = make_float4(0.f,0.f,0.f,0.f);
    int row0 = b*Nn + chunk*RPB;

    for (int r = 0; r < RPB; r++){
        int row = row0 + r;
        size_t base = (size_t)row * Dd;
        float mk = __ldg(mask + row);
        float e2 = g_e[k][row];
        float q  = __ldg(q0 + row);
        float rkm = rk * mk;

        float4 xv = __ldcs(&((const float4*)(x + base))[tid]);
        float4 zv = make_float4(0.f,0.f,0.f,0.f);
        if (MODE != 0) zv = ((const float4*)(g_z + base))[tid];

        float4 gv;
        gv.x = lg2(fmaf(q, pv.x, EPSc));
        gv.y = lg2(fmaf(q, pv.y, EPSc));
        gv.z = lg2(fmaf(q, pv.z, EPSc));
        gv.w = lg2(fmaf(q, pv.w, EPSc));

        float4 lt;
        if (MODE == 0){
            float Lr0 = g_Lrow[0][row];
            lt.x = AorM.x + fmaf(xv.x, invrk2, gv.x) - Lr0;
            lt.y = AorM.y + fmaf(xv.y, invrk2, gv.y) - Lr0;
            lt.z = AorM.z + fmaf(xv.z, invrk2, gv.z) - Lr0;
            lt.w = AorM.w + fmaf(xv.w, invrk2, gv.w) - Lr0;
        } else {
            float Brow = g_B[k][row];
            lt.x = (xv.x - zv.x)*invrk2 + fmaf(al, xv.x, fmaf(be, gv.x, skdrk*(AorM.x + Brow)));
            lt.y = (xv.y - zv.y)*invrk2 + fmaf(al, xv.y, fmaf(be, gv.y, skdrk*(AorM.y + Brow)));
            lt.z = (xv.z - zv.z)*invrk2 + fmaf(al, xv.z, fmaf(be, gv.z, skdrk*(AorM.z + Brow)));
            lt.w = (xv.w - zv.w)*invrk2 + fmaf(al, xv.w, fmaf(be, gv.w, skdrk*(AorM.w + Brow)));
        }

        float4 y, zn;
        {
            float U, ls;
            U = fmaf(zv.x, il2sk, lt.x*rkdsk);  ls = e2 - Lc.x + U;
            zn.x = fmaf(rkm, ex2(lt.x) - ex2(ls), zv.x);
            y.x  = fmaf(xv.x - zn.x, invrn2, ls);
            U = fmaf(zv.y, il2sk, lt.y*rkdsk);  ls = e2 - Lc.y + U;
            zn.y = fmaf(rkm, ex2(lt.y) - ex2(ls), zv.y);
            y.y  = fmaf(xv.y - zn.y, invrn2, ls);
            U = fmaf(zv.z, il2sk, lt.z*rkdsk);  ls = e2 - Lc.z + U;
            zn.z = fmaf(rkm, ex2(lt.z) - ex2(ls), zv.z);
            y.z  = fmaf(xv.z - zn.z, invrn2, ls);
            U = fmaf(zv.w, il2sk, lt.w*rkdsk);  ls = e2 - Lc.w + U;
            zn.w = fmaf(rkm, ex2(lt.w) - ex2(ls), zv.w);
            y.w  = fmaf(xv.w - zn.w, invrn2, ls);
        }

        // one-barrier block LSE over y (512 values)
        float mx = fmaxf(fmaxf(y.x, y.y), fmaxf(y.z, y.w));
        mx = warpMax(mx);
        float se = ex2(y.x-mx) + ex2(y.y-mx) + ex2(y.z-mx) + ex2(y.w-mx);
        se = warpSum(se);
        int pb = r & 1;
        if (lane == 0){ sm_m[pb][wid] = mx; sm_s[pb][wid] = se; }
        __syncthreads();
        float M0 = sm_m[pb][0], M1 = sm_m[pb][1], M2v = sm_m[pb][2], M3 = sm_m[pb][3];
        float Mf = fmaxf(fmaxf(M0, M1), fmaxf(M2v, M3));
        float Sf = sm_s[pb][0]*ex2(M0-Mf) + sm_s[pb][1]*ex2(M1-Mf)
                 + sm_s[pb][2]*ex2(M2v-Mf) + sm_s[pb][3]*ex2(M3-Mf);
        float L2 = Mf + lg2(Sf);

        if (MODE == 2){
            float4 o;
            o.x = ex2(mn.x + y.x - L2)*mk;
            o.y = ex2(mn.y + y.y - L2)*mk;
            o.z = ex2(mn.z + y.z - L2)*mk;
            o.w = ex2(mn.w + y.w - L2)*mk;
            __stcs(&((float4*)(out + base))[tid], o);
        } else {
            ((float4*)(g_z + base))[tid] = zn;
            if (tid == 0) g_Lrow[k+1][row] = L2;
            // U_{k+1} = zn*il2sn + lt'*rndsn ; accumulate 2^(U - Lc_k[d])
            float o0 = mn.x + y.x - L2;
            float o1 = mn.y + y.y - L2;
            float o2 = mn.z + y.z - L2;
            float o3 = mn.w + y.w - L2;
            acc.x += ex2(fmaf(zn.x, il2sn, o0*rndsn) - Lc.x);
            acc.y += ex2(fmaf(zn.y, il2sn, o1*rndsn) - Lc.y);
            acc.z += ex2(fmaf(zn.z, il2sn, o2*rndsn) - Lc.z);
            acc.w += ex2(fmaf(zn.w, il2sn, o3*rndsn) - Lc.w);
        }
    }
    if (MODE != 2)
        ((float4*)(g_Sp + (size_t)bc*Dd))[tid] = acc;
}

// ---------------------------------------------------------------------------
extern "C" void kernel_launch(void* const* d_in, const int* in_sizes, int n_in,
                              void* d_out, int out_size)
{
    const float* x    = (const float*)d_in[0];
    const float* p0   = (const float*)d_in[1];
    const float* q0   = (const float*)d_in[2];
    const float* a1   = (const float*)d_in[3];
    const float* a2   = (const float*)d_in[4];
    const float* a3   = (const float*)d_in[5];
    const float* rho  = (const float*)d_in[6];
    const float* mask = (const float*)d_in[7];
    float* out = (float*)d_out;

    precomp_kernel<<<Bb, 512>>>(p0, q0, a2, a3, rho, a1);
    row0lse_kernel<<<Bb*CH, 128>>>(x, p0, q0);

    tables_kernel<<<Bb, 512>>>(rho, a1, 0);
    fused_kernel<0><<<Bb*CH, 128>>>(x, p0, q0, mask, out);

    tables_kernel<<<Bb, 512>>>(rho, a1, 1);
    fused_kernel<1><<<Bb*CH, 128>>>(x, p0, q0, mask, out);

    tables_kernel<<<Bb, 512>>>(rho, a1, 2);
    fused_kernel<2><<<Bb*CH, 128>>>(x, p0, q0, mask, out);
}